// round 13
// baseline (speedup 1.0000x reference)
#include <cuda_runtime.h>
#include <cuda_bf16.h>
#include <cstdint>
#include <cstddef>
#include <math.h>

#define BATCH 32
#define SEQ   64
#define HID   1024
#define EMB   512
#define VOC   32000
#define G3    3072
#define ROWS  2048   // SEQ*BATCH
#define LNB   250    // VOC/128 logits col-blocks

#define NBLK  128    // persistent scan blocks (HID/8)
#define SNTHR 512    // 16 warps

// padded smem row stride for bf16 weight/activation tiles: 1024 + 8 elems
#define RSTRIDE 1032           // elements
#define RSTRIDE_B 2064         // bytes

// enc smem carve
#define ENC_W_BYTES   (24 * RSTRIDE_B)
#define ENC_HS_OFF    ENC_W_BYTES
#define ENC_GRED_OFF  (ENC_HS_OFF + 32 * RSTRIDE_B)
#define ENC_SM_TOTAL  (ENC_GRED_OFF + 8 * 32 * 24 * 4)

// dec smem carve
#define DEC_W_BYTES   (56 * RSTRIDE_B)
#define DEC_HS_OFF    DEC_W_BYTES
#define DEC_GRED_OFF  (DEC_HS_OFF + 32 * RSTRIDE_B)
#define DEC_WHRED_OFF (DEC_GRED_OFF + 8 * 32 * 24 * 4)
#define DEC_SSC_OFF   (DEC_WHRED_OFF + 8 * 32 * 8 * 4)
#define DEC_SM_TOTAL  (DEC_SSC_OFF + SEQ * 4)

// ------------------------------ scratch ---------------------------------
__device__ float g_enc_xg[ROWS * G3];
__device__ float g_dec_xg[ROWS * G3];
__device__ float g_enc_outs[ROWS * HID];
__device__ float g_enc_energy[ROWS * HID];
__device__ float g_hbuf[2][BATCH * HID];
__device__ float g_wh[BATCH * HID];
__device__ float g_scores[BATCH * SEQ];
__device__ float g_tok_lp[ROWS];
__device__ float g_tgtlog[ROWS];
__device__ int   g_gidx_enc[ROWS];
__device__ int   g_gidx_dec[ROWS];
__device__ int   g_tgtcol[ROWS];
__device__ __align__(16) float2 g_part[(size_t)ROWS * LNB];
__device__ unsigned g_bar_grp[8];
__device__ unsigned g_bar_arrive = 0;
__device__ volatile unsigned g_bar_phase = 0;
__device__ volatile unsigned g_sbar[BATCH];

// bf16 operands
__device__ __align__(16) __nv_bfloat16 g_encA_bf[ROWS * EMB];
__device__ __align__(16) __nv_bfloat16 g_decA_bf[ROWS * EMB];
__device__ __align__(16) __nv_bfloat16 g_encWih_bf[G3 * EMB];
__device__ __align__(16) __nv_bfloat16 g_decWih_bf[G3 * EMB];
__device__ __align__(16) __nv_bfloat16 g_We_bf[HID * HID];
__device__ __align__(16) __nv_bfloat16 g_Wh_bf[HID * HID];
__device__ __align__(16) __nv_bfloat16 g_Wout_bf[(size_t)VOC * HID];
__device__ __align__(16) __nv_bfloat16 g_encouts_bf[ROWS * HID];
__device__ __align__(16) __nv_bfloat16 g_dech_bf[ROWS * HID];
__device__ __align__(16) __nv_bfloat16 g_encWhh_bf[G3 * HID];
__device__ __align__(16) __nv_bfloat16 g_decWhh_bf[G3 * HID];
__device__ __align__(16) __nv_bfloat16 g_decWch_bf[G3 * HID];
__device__ __align__(16) __nv_bfloat16 g_hbuf_bf[2][BATCH * HID];
__device__ __align__(16) __nv_bfloat16 g_ctx_bf[BATCH * HID];

// ------------------------------ helpers ---------------------------------
__device__ __forceinline__ float tanh_approx(float x) {
    float y; asm("tanh.approx.f32 %0, %1;" : "=f"(y) : "f"(x)); return y;
}

// two-level tree barrier: 8 groups of 16 blocks. Release by last arriver.
__device__ __forceinline__ void grid_sync() {
    __syncthreads();
    if (threadIdx.x == 0) {
        __threadfence();
        unsigned ph = g_bar_phase;
        int grp = blockIdx.x >> 4;
        unsigned a = atomicAdd(&g_bar_grp[grp], 1u);
        if (a == 15u) {
            unsigned b = atomicAdd(&g_bar_arrive, 1u);
            if (b == 7u) {
                g_bar_arrive = 0u;
#pragma unroll
                for (int g = 0; g < 8; g++) g_bar_grp[g] = 0u;
                __threadfence();
                g_bar_phase = ph + 1u;
            } else {
                while (g_bar_phase == ph) { __nanosleep(32); }
            }
        } else {
            while (g_bar_phase == ph) { __nanosleep(32); }
        }
    }
    __syncthreads();
}

__device__ __forceinline__ void group_sync4(int b2, unsigned target) {
    __syncthreads();
    if (threadIdx.x == 0) {
        __threadfence();
        atomicAdd((unsigned*)&g_sbar[b2], 1u);
        while (g_sbar[b2] < target) { }
        __threadfence();
    }
    __syncthreads();
}

__device__ __forceinline__ unsigned int smem_u32(const void* p) {
    return (unsigned int)__cvta_generic_to_shared(p);
}
__device__ __forceinline__ void cp16(unsigned int dst, const void* src, bool pred) {
    int sz = pred ? 16 : 0;
    asm volatile("cp.async.cg.shared.global [%0], [%1], 16, %2;\n"
                 :: "r"(dst), "l"(src), "r"(sz));
}
__device__ __forceinline__ void cp_commit() { asm volatile("cp.async.commit_group;\n"); }
__device__ __forceinline__ void cp_wait0()  { asm volatile("cp.async.wait_group 0;\n"); }
__device__ __forceinline__ void ldsm_x4(unsigned int& r0, unsigned int& r1,
                                        unsigned int& r2, unsigned int& r3, unsigned int a) {
    asm volatile("ldmatrix.sync.aligned.m8n8.x4.shared.b16 {%0,%1,%2,%3},[%4];"
                 : "=r"(r0), "=r"(r1), "=r"(r2), "=r"(r3) : "r"(a));
}
__device__ __forceinline__ void ldsm_x2(unsigned int& r0, unsigned int& r1, unsigned int a) {
    asm volatile("ldmatrix.sync.aligned.m8n8.x2.shared.b16 {%0,%1},[%2];"
                 : "=r"(r0), "=r"(r1) : "r"(a));
}
__device__ __forceinline__ void mma16816(float* c, unsigned int a0, unsigned int a1,
                                         unsigned int a2, unsigned int a3,
                                         unsigned int b0, unsigned int b1) {
    asm volatile("mma.sync.aligned.m16n8k16.row.col.f32.bf16.bf16.f32 "
                 "{%0,%1,%2,%3},{%4,%5,%6,%7},{%8,%9},{%0,%1,%2,%3};"
                 : "+f"(c[0]), "+f"(c[1]), "+f"(c[2]), "+f"(c[3])
                 : "r"(a0), "r"(a1), "r"(a2), "r"(a3), "r"(b0), "r"(b1));
}

// --------------------------- gather indices -----------------------------
__global__ void build_gather(const int* __restrict__ s, const int* __restrict__ t) {
    int r = blockIdx.x * blockDim.x + threadIdx.x;
    if (blockIdx.x == 0 && threadIdx.x < BATCH) g_sbar[threadIdx.x] = 0u;
    if (r >= ROWS) return;
    int sp = r >> 5, b = r & 31;
    g_gidx_enc[r] = s[b * SEQ + sp];
    g_gidx_dec[r] = (sp == 0) ? -1 : t[b * SEQ + sp - 1];
    g_tgtcol[r] = t[b * SEQ + sp];
}

// ------------------- gathered embedding rows -> bf16 ---------------------
__global__ void __launch_bounds__(256) conv_emb(const float* __restrict__ emb) {
    long long e = ((long long)blockIdx.x * blockDim.x + threadIdx.x) * 8;
    if (e >= 2LL * ROWS * EMB) return;
    int which = (e >= (long long)ROWS * EMB);
    long long off = e - (long long)which * ROWS * EMB;
    int r = (int)(off >> 9);
    int c = (int)(off & (EMB - 1));
    int idx = which ? g_gidx_dec[r] : g_gidx_enc[r];
    __nv_bfloat16* dst = which ? g_decA_bf : g_encA_bf;
    __nv_bfloat16 o[8];
    if (idx < 0) {
#pragma unroll
        for (int k = 0; k < 8; k++) o[k] = __float2bfloat16(0.f);
    } else {
        const float* src = emb + (size_t)idx * EMB + c;
        float4 v0 = *(const float4*)src;
        float4 v1 = *(const float4*)(src + 4);
        o[0] = __float2bfloat16(v0.x); o[1] = __float2bfloat16(v0.y);
        o[2] = __float2bfloat16(v0.z); o[3] = __float2bfloat16(v0.w);
        o[4] = __float2bfloat16(v1.x); o[5] = __float2bfloat16(v1.y);
        o[6] = __float2bfloat16(v1.z); o[7] = __float2bfloat16(v1.w);
    }
    *(uint4*)(dst + off) = *(const uint4*)o;
}

// ---------------------------- fp32 -> bf16 (weights) ---------------------
#define CVO1 (G3 * EMB)
#define CVO2 (CVO1 + G3 * EMB)
#define CVO3 (CVO2 + VOC * HID)
#define CVO4 (CVO3 + G3 * HID)
#define CVO5 (CVO4 + G3 * HID)
#define CVEND (CVO5 + G3 * HID)
__global__ void __launch_bounds__(256) conv_all(
    const float* __restrict__ eWih, const float* __restrict__ dWih,
    const float* __restrict__ Wout, const float* __restrict__ eWhh,
    const float* __restrict__ dWhh, const float* __restrict__ dWch)
{
    long long e = ((long long)blockIdx.x * blockDim.x + threadIdx.x) * 8;
    if (e >= CVEND) return;
    const float* src;
    __nv_bfloat16* dst;
    long long off;
    if (e < CVO1)      { src = eWih; dst = g_encWih_bf; off = e; }
    else if (e < CVO2) { src = dWih; dst = g_decWih_bf; off = e - CVO1; }
    else if (e < CVO3) { src = Wout; dst = g_Wout_bf;   off = e - CVO2; }
    else if (e < CVO4) { src = eWhh; dst = g_encWhh_bf; off = e - CVO3; }
    else if (e < CVO5) { src = dWhh; dst = g_decWhh_bf; off = e - CVO4; }
    else               { src = dWch; dst = g_decWch_bf; off = e - CVO5; }
    float4 v0 = *(const float4*)(src + off);
    float4 v1 = *(const float4*)(src + off + 4);
    __nv_bfloat16 o[8];
    o[0] = __float2bfloat16(v0.x); o[1] = __float2bfloat16(v0.y);
    o[2] = __float2bfloat16(v0.z); o[3] = __float2bfloat16(v0.w);
    o[4] = __float2bfloat16(v1.x); o[5] = __float2bfloat16(v1.y);
    o[6] = __float2bfloat16(v1.z); o[7] = __float2bfloat16(v1.w);
    *(uint4*)(dst + off) = *(const uint4*)o;
}

__global__ void conv_attnW(const float* __restrict__ attn_W) {
    int i = blockIdx.x * blockDim.x + threadIdx.x;
    if (i < HID * HID) {
        int j = i >> 10;
        int k = i & 1023;
        g_We_bf[i] = __float2bfloat16(attn_W[(size_t)j * 2048 + 1024 + k]);
        g_Wh_bf[i] = __float2bfloat16(attn_W[(size_t)j * 2048 + k]);
    }
}

// ---------------------------- bf16 HMMA GEMM -----------------------------
#define PADK 40
__global__ void __launch_bounds__(256) hgemm(int which, const float* __restrict__ bias)
{
    __shared__ __nv_bfloat16 As[2][128][PADK];
    __shared__ __nv_bfloat16 Bs[2][128][PADK];
    const unsigned int STG = 128 * PADK * 2;

    const __nv_bfloat16* A;
    const __nv_bfloat16* Wb;
    float* C;
    int N, K;
    if (which == 0) {
        A = g_encA_bf; Wb = g_encWih_bf; C = g_enc_xg; N = G3; K = EMB;
    } else if (which == 1) {
        A = g_decA_bf; Wb = g_decWih_bf; C = g_dec_xg; N = G3; K = EMB;
    } else if (which == 2) {
        A = g_encouts_bf; Wb = g_We_bf; C = g_enc_energy; N = HID; K = HID;
    } else {
        A = g_dech_bf; Wb = g_Wout_bf; C = (float*)0; N = VOC; K = HID;
    }

    int tid = threadIdx.x;
    int bn = blockIdx.x, bm = blockIdx.y;
    int warp = tid >> 5, lane = tid & 31;
    int wm = warp >> 2, wn = warp & 3;

    int lr = tid >> 2;
    int lc = (tid & 3) * 8;

    const __nv_bfloat16* a0 = A + (size_t)(bm * 128 + lr) * K;
    const __nv_bfloat16* a1 = A + (size_t)(bm * 128 + lr + 64) * K;
    const __nv_bfloat16* b0p = Wb + (size_t)(bn * 128 + lr) * K;
    const __nv_bfloat16* b1p = Wb + (size_t)(bn * 128 + lr + 64) * K;

    unsigned int sa0 = smem_u32(&As[0][lr][lc]);
    unsigned int sa1 = smem_u32(&As[0][lr + 64][lc]);
    unsigned int sb0 = smem_u32(&Bs[0][lr][lc]);
    unsigned int sb1 = smem_u32(&Bs[0][lr + 64][lc]);

    float acc[4][4][4];
#pragma unroll
    for (int mi = 0; mi < 4; mi++) {
#pragma unroll
        for (int ni = 0; ni < 4; ni++) {
#pragma unroll
            for (int q = 0; q < 4; q++) acc[mi][ni][q] = 0.f;
        }
    }

    int arow = wm * 64 + (lane & 15);
    int acol_off = (lane >> 4) * 8;
    int brow = wn * 32 + (lane & 7);
    int bcol_off = ((lane >> 3) & 1) * 8;

    int KT = K / 32;
    cp16(sa0, a0 + lc, true);
    cp16(sa1, a1 + lc, true);
    cp16(sb0, b0p + lc, true);
    cp16(sb1, b1p + lc, true);
    cp_commit();

    int stage = 0;
    for (int kt = 0; kt < KT; kt++) {
        cp_wait0();
        __syncthreads();
        if (kt + 1 < KT) {
            int k = (kt + 1) * 32;
            unsigned int off = (unsigned int)(stage ^ 1) * STG;
            cp16(sa0 + off, a0 + k + lc, true);
            cp16(sa1 + off, a1 + k + lc, true);
            cp16(sb0 + off, b0p + k + lc, true);
            cp16(sb1 + off, b1p + k + lc, true);
            cp_commit();
        }
#pragma unroll
        for (int ks = 0; ks < 32; ks += 16) {
            unsigned int af[4][4];
#pragma unroll
            for (int mi = 0; mi < 4; mi++) {
                unsigned int addr = smem_u32(&As[stage][arow + mi * 16][ks + acol_off]);
                ldsm_x4(af[mi][0], af[mi][1], af[mi][2], af[mi][3], addr);
            }
            unsigned int bfr[4][2];
#pragma unroll
            for (int ni = 0; ni < 4; ni++) {
                unsigned int addr = smem_u32(&Bs[stage][brow + ni * 8][ks + bcol_off]);
                ldsm_x2(bfr[ni][0], bfr[ni][1], addr);
            }
#pragma unroll
            for (int mi = 0; mi < 4; mi++) {
#pragma unroll
                for (int ni = 0; ni < 4; ni++) {
                    mma16816(acc[mi][ni], af[mi][0], af[mi][1], af[mi][2], af[mi][3],
                             bfr[ni][0], bfr[ni][1]);
                }
            }
        }
        stage ^= 1;
    }

    int row_base = bm * 128 + wm * 64;
    int col_base = bn * 128 + wn * 32;

    if (which == 3) {
        float* pm = (float*)&As[0][0][0];
        float* ps = pm + 512;
        float bb2[4][2];
#pragma unroll
        for (int ni = 0; ni < 4; ni++) {
            int c0 = col_base + ni * 8 + (lane & 3) * 2;
            bb2[ni][0] = __ldg(bias + c0);
            bb2[ni][1] = __ldg(bias + c0 + 1);
        }
        __syncthreads();
#pragma unroll
        for (int mi = 0; mi < 4; mi++) {
#pragma unroll
            for (int h = 0; h < 2; h++) {
                int rloc = wm * 64 + mi * 16 + (lane >> 2) + 8 * h;
                int grow = bm * 128 + rloc;
                int tc = g_tgtcol[grow] - bn * 128;
                float v[8];
                float m = -3.4e38f;
#pragma unroll
                for (int ni = 0; ni < 4; ni++) {
#pragma unroll
                    for (int q = 0; q < 2; q++) {
                        float x = acc[mi][ni][2 * h + q] + bb2[ni][q];
                        v[ni * 2 + q] = x;
                        m = fmaxf(m, x);
                        int cl = wn * 32 + ni * 8 + (lane & 3) * 2 + q;
                        if (cl == tc) g_tgtlog[grow] = x;
                    }
                }
                float ssum = 0.f;
#pragma unroll
                for (int k2 = 0; k2 < 8; k2++) ssum += __expf(v[k2] - m);
#pragma unroll
                for (int off = 1; off <= 2; off <<= 1) {
                    float mo = __shfl_xor_sync(0xffffffffu, m, off);
                    float so = __shfl_xor_sync(0xffffffffu, ssum, off);
                    float M = fmaxf(m, mo);
                    ssum = ssum * __expf(m - M) + so * __expf(mo - M);
                    m = M;
                }
                if ((lane & 3) == 0) { pm[rloc * 4 + wn] = m; ps[rloc * 4 + wn] = ssum; }
            }
        }
        __syncthreads();
        if (tid < 128) {
            float m = pm[tid * 4], s2 = ps[tid * 4];
#pragma unroll
            for (int w2 = 1; w2 < 4; w2++) {
                float mo = pm[tid * 4 + w2], so = ps[tid * 4 + w2];
                float M = fmaxf(m, mo);
                s2 = s2 * __expf(m - M) + so * __expf(mo - M);
                m = M;
            }
            g_part[(size_t)(bm * 128 + tid) * LNB + bn] = make_float2(m, s2);
        }
        return;
    }

#pragma unroll
    for (int mi = 0; mi < 4; mi++) {
#pragma unroll
        for (int ni = 0; ni < 4; ni++) {
            int r0 = row_base + mi * 16 + (lane >> 2);
            int c0 = col_base + ni * 8 + (lane & 3) * 2;
            float bv0 = bias ? __ldg(bias + c0) : 0.f;
            float bv1 = bias ? __ldg(bias + c0 + 1) : 0.f;
            float2 v0 = make_float2(acc[mi][ni][0] + bv0, acc[mi][ni][1] + bv1);
            float2 v1 = make_float2(acc[mi][ni][2] + bv0, acc[mi][ni][3] + bv1);
            *(float2*)(C + (size_t)r0 * N + c0) = v0;
            *(float2*)(C + (size_t)(r0 + 8) * N + c0) = v1;
        }
    }
}

// ---------------------------- encoder scan (HMMA) ------------------------
__global__ void __launch_bounds__(SNTHR) enc_scan(const float* __restrict__ bhh)
{
    extern __shared__ char sm[];
    __nv_bfloat16* Wsm = (__nv_bfloat16*)sm;
    __nv_bfloat16* hs  = (__nv_bfloat16*)(sm + ENC_HS_OFF);
    float* Gred        = (float*)(sm + ENC_GRED_OFF);

    int tid = threadIdx.x;
    int w = tid >> 5, lane = tid & 31;
    int mw = w & 1, kw = w >> 1;
    int j0 = blockIdx.x * 8;

    for (int f = tid; f < 24 * 128; f += SNTHR) {
        int r = f >> 7, c = f & 127;
        int grow = (r < 8) ? (j0 + r) : (r < 16) ? (1024 + j0 + r - 8) : (2048 + j0 + r - 16);
        cp16(smem_u32(Wsm + r * RSTRIDE + c * 8), g_encWhh_bf + (size_t)grow * HID + c * 8, true);
    }
    cp_commit();
    for (int i = blockIdx.x * SNTHR + tid; i < BATCH * HID; i += NBLK * SNTHR) {
        g_hbuf[0][i] = 0.f;
        g_hbuf_bf[0][i] = __float2bfloat16(0.f);
    }
    cp_wait0();
    __syncthreads();
    grid_sync();

    int jj = tid & 7, b = tid >> 3;
    float br = 0.f, bz = 0.f, bn_ = 0.f;
    if (tid < 256) {
        br = bhh[j0 + jj]; bz = bhh[1024 + j0 + jj]; bn_ = bhh[2048 + j0 + jj];
    }

    unsigned int aBase = smem_u32(hs) + (unsigned)((mw * 16 + (lane & 15)) * RSTRIDE_B + ((lane >> 4) * 8) * 2);
    unsigned int bBase = smem_u32(Wsm) + (unsigned)((lane & 7) * RSTRIDE_B + (((lane >> 3) & 1) * 8) * 2);

    for (int s = 0; s < SEQ; s++) {
        int hb = s & 1;
        for (int f = tid; f < 32 * 128; f += SNTHR) {
            int r = f >> 7, c = f & 127;
            cp16(smem_u32(hs + r * RSTRIDE + c * 8), g_hbuf_bf[hb] + r * HID + c * 8, true);
        }
        cp_commit(); cp_wait0(); __syncthreads();

        float cG[3][4];
#pragma unroll
        for (int nt = 0; nt < 3; nt++) {
#pragma unroll
            for (int q = 0; q < 4; q++) cG[nt][q] = 0.f;
        }
#pragma unroll
        for (int kt = 0; kt < 8; kt++) {
            int k16 = kw * 8 + kt;
            unsigned int a0, a1, a2, a3;
            ldsm_x4(a0, a1, a2, a3, aBase + k16 * 32);
#pragma unroll
            for (int nt = 0; nt < 3; nt++) {
                unsigned int b0, b1;
                ldsm_x2(b0, b1, bBase + nt * 8 * RSTRIDE_B + k16 * 32);
                mma16816(cG[nt], a0, a1, a2, a3, b0, b1);
            }
        }
        {
            int r0 = lane >> 2, c0 = (lane & 3) * 2;
            int bb = mw * 16 + r0;
#pragma unroll
            for (int nt = 0; nt < 3; nt++) {
                Gred[(kw * 32 + bb) * 24 + nt * 8 + c0]         = cG[nt][0];
                Gred[(kw * 32 + bb) * 24 + nt * 8 + c0 + 1]     = cG[nt][1];
                Gred[(kw * 32 + bb + 8) * 24 + nt * 8 + c0]     = cG[nt][2];
                Gred[(kw * 32 + bb + 8) * 24 + nt * 8 + c0 + 1] = cG[nt][3];
            }
        }
        __syncthreads();
        if (tid < 256) {
            float hr = 0.f, hz = 0.f, hn = 0.f;
#pragma unroll
            for (int k = 0; k < 8; k++) {
                int base2 = (k * 32 + b) * 24;
                hr += Gred[base2 + jj];
                hz += Gred[base2 + 8 + jj];
                hn += Gred[base2 + 16 + jj];
            }
            int row = s * BATCH + b;
            int j = j0 + jj;
            const float* xg = g_enc_xg + (size_t)row * G3;
            float xr = __ldg(xg + j), xz = __ldg(xg + 1024 + j), xn = __ldg(xg + 2048 + j);
            float hprev = g_hbuf[hb][b * HID + j];
            float r = 1.f / (1.f + expf(-(xr + hr + br)));
            float z = 1.f / (1.f + expf(-(xz + hz + bz)));
            float n = tanhf(xn + r * (hn + bn_));
            float hnew = (1.f - z) * n + z * hprev;
            g_hbuf[hb ^ 1][b * HID + j] = hnew;
            __nv_bfloat16 h16 = __float2bfloat16(hnew);
            g_hbuf_bf[hb ^ 1][b * HID + j] = h16;
            g_enc_outs[(size_t)row * HID + j] = hnew;
            g_encouts_bf[(size_t)row * HID + j] = h16;
        }
        grid_sync();
    }
}

// ---------------------------- decoder scan (HMMA) ------------------------
__global__ void __launch_bounds__(SNTHR) dec_scan(const float* __restrict__ bhh,
                                                  const float* __restrict__ attn_v)
{
    extern __shared__ char sm[];
    __nv_bfloat16* Wsm = (__nv_bfloat16*)sm;
    __nv_bfloat16* hs  = (__nv_bfloat16*)(sm + DEC_HS_OFF);
    float* Gred        = (float*)(sm + DEC_GRED_OFF);
    float* whred       = (float*)(sm + DEC_WHRED_OFF);
    float* s_sc        = (float*)(sm + DEC_SSC_OFF);

    int tid = threadIdx.x;
    int w = tid >> 5, lane = tid & 31;
    int mw = w & 1, kw = w >> 1;
    int j0 = blockIdx.x * 8;

    for (int f = tid; f < 56 * 128; f += SNTHR) {
        int r = f >> 7, c = f & 127;
        const __nv_bfloat16* src;
        if (r < 24) {
            int grow = (r < 8) ? (j0 + r) : (r < 16) ? (1024 + j0 + r - 8) : (2048 + j0 + r - 16);
            src = g_decWhh_bf + (size_t)grow * HID;
        } else if (r < 48) {
            int rr = r - 24;
            int grow = (rr < 8) ? (j0 + rr) : (rr < 16) ? (1024 + j0 + rr - 8) : (2048 + j0 + rr - 16);
            src = g_decWch_bf + (size_t)grow * HID;
        } else {
            src = g_Wh_bf + (size_t)(j0 + r - 48) * HID;
        }
        cp16(smem_u32(Wsm + r * RSTRIDE + c * 8), src + c * 8, true);
    }
    cp_commit(); cp_wait0(); __syncthreads();
    grid_sync();

    int jj = tid & 7, b = tid >> 3;
    float br = 0.f, bz = 0.f, bn_ = 0.f;
    if (tid < 256) {
        br = bhh[j0 + jj]; bz = bhh[1024 + j0 + jj]; bn_ = bhh[2048 + j0 + jj];
    }

    unsigned int aBase = smem_u32(hs) + (unsigned)((mw * 16 + (lane & 15)) * RSTRIDE_B + ((lane >> 4) * 8) * 2);
    unsigned int bBase = smem_u32(Wsm) + (unsigned)((lane & 7) * RSTRIDE_B + (((lane >> 3) & 1) * 8) * 2);

    float hr = 0.f, hz = 0.f, hn = 0.f;
    int b2 = blockIdx.x & 31;

    for (int s = 0; s < SEQ; s++) {
        int hb = s & 1;

        for (int f = tid; f < 32 * 128; f += SNTHR) {
            int r = f >> 7, c = f & 127;
            cp16(smem_u32(hs + r * RSTRIDE + c * 8), g_hbuf_bf[hb] + r * HID + c * 8, true);
        }
        cp_commit(); cp_wait0(); __syncthreads();

        float cG[3][4], cW[4];
#pragma unroll
        for (int nt = 0; nt < 3; nt++) {
#pragma unroll
            for (int q = 0; q < 4; q++) cG[nt][q] = 0.f;
        }
#pragma unroll
        for (int q = 0; q < 4; q++) cW[q] = 0.f;
#pragma unroll
        for (int kt = 0; kt < 8; kt++) {
            int k16 = kw * 8 + kt;
            unsigned int a0, a1, a2, a3;
            ldsm_x4(a0, a1, a2, a3, aBase + k16 * 32);
#pragma unroll
            for (int nt = 0; nt < 3; nt++) {
                unsigned int b0, b1;
                ldsm_x2(b0, b1, bBase + nt * 8 * RSTRIDE_B + k16 * 32);
                mma16816(cG[nt], a0, a1, a2, a3, b0, b1);
            }
            unsigned int b0, b1;
            ldsm_x2(b0, b1, bBase + 48 * RSTRIDE_B + k16 * 32);
            mma16816(cW, a0, a1, a2, a3, b0, b1);
        }
        {
            int r0 = lane >> 2, c0 = (lane & 3) * 2;
            int bb = mw * 16 + r0;
#pragma unroll
            for (int nt = 0; nt < 3; nt++) {
                Gred[(kw * 32 + bb) * 24 + nt * 8 + c0]         = cG[nt][0];
                Gred[(kw * 32 + bb) * 24 + nt * 8 + c0 + 1]     = cG[nt][1];
                Gred[(kw * 32 + bb + 8) * 24 + nt * 8 + c0]     = cG[nt][2];
                Gred[(kw * 32 + bb + 8) * 24 + nt * 8 + c0 + 1] = cG[nt][3];
            }
            whred[(kw * 32 + bb) * 8 + c0]         = cW[0];
            whred[(kw * 32 + bb) * 8 + c0 + 1]     = cW[1];
            whred[(kw * 32 + bb + 8) * 8 + c0]     = cW[2];
            whred[(kw * 32 + bb + 8) * 8 + c0 + 1] = cW[3];
        }
        __syncthreads();
        if (tid < 256) {
            float whv = 0.f;
            hr = 0.f; hz = 0.f; hn = 0.f;
#pragma unroll
            for (int k = 0; k < 8; k++) {
                int base2 = k * 32 + b;
                whv += whred[base2 * 8 + jj];
                hr += Gred[base2 * 24 + jj];
                hz += Gred[base2 * 24 + 8 + jj];
                hn += Gred[base2 * 24 + 16 + jj];
            }
            g_wh[b * HID + j0 + jj] = whv;
        }
        grid_sync();

        {
            int sp = (blockIdx.x >> 5) * 16 + w;
            const float* ee = g_enc_energy + (size_t)(sp * BATCH + b2) * HID;
            const float* whp = g_wh + b2 * HID;
            float acc = 0.f;
            for (int k = lane; k < HID; k += 32)
                acc += tanh_approx(__ldg(ee + k) + __ldcg(whp + k)) * __ldg(attn_v + k);
#pragma unroll
            for (int o = 16; o; o >>= 1) acc += __shfl_xor_sync(0xffffffffu, acc, o);
            if (lane == 0) g_scores[b2 * SEQ + sp] = acc;
        }
        group_sync4(b2, 4u * (unsigned)(s + 1));

        {
            int jq = blockIdx.x >> 5;
            if (tid < SEQ) s_sc[tid] = __ldcg(g_scores + b2 * SEQ + tid);
            __syncthreads();
            if (w == 0) {
                float v0 = s_sc[lane], v1 = s_sc[lane + 32];
                float m = fmaxf(v0, v1);
#pragma unroll
                for (int o = 16; o; o >>= 1) m = fmaxf(m, __shfl_xor_sync(0xffffffffu, m, o));
                float e0 = expf(v0 - m), e1 = expf(v1 - m);
                float ssum = e0 + e1;
#pragma unroll
                for (int o = 16; o; o >>= 1) ssum += __shfl_xor_sync(0xffffffffu, ssum, o);
                float inv = 1.f / ssum;
                s_sc[lane] = e0 * inv; s_sc[lane + 32] = e1 * inv;
            }
            __syncthreads();
            if (tid < 256) {
                int jx = jq * 256 + tid;
                float a0 = 0.f, a1 = 0.f, a2 = 0.f, a3 = 0.f;
#pragma unroll 4
                for (int sp = 0; sp < SEQ; sp += 4) {
                    a0 += s_sc[sp]     * __ldg(g_enc_outs + (size_t)((sp)     * BATCH + b2) * HID + jx);
                    a1 += s_sc[sp + 1] * __ldg(g_enc_outs + (size_t)((sp + 1) * BATCH + b2) * HID + jx);
                    a2 += s_sc[sp + 2] * __ldg(g_enc_outs + (size_t)((sp + 2) * BATCH + b2) * HID + jx);
                    a3 += s_sc[sp + 3] * __ldg(g_enc_outs + (size_t)((sp + 3) * BATCH + b2) * HID + jx);
                }
                g_ctx_bf[b2 * HID + jx] = __float2bfloat16((a0 + a1) + (a2 + a3));
            }
        }
        grid_sync();

        for (int f = tid; f < 32 * 128; f += SNTHR) {
            int r = f >> 7, c = f & 127;
            cp16(smem_u32(hs + r * RSTRIDE + c * 8), g_ctx_bf + r * HID + c * 8, true);
        }
        cp_commit(); cp_wait0(); __syncthreads();

        float cC[3][4];
#pragma unroll
        for (int nt = 0; nt < 3; nt++) {
#pragma unroll
            for (int q = 0; q < 4; q++) cC[nt][q] = 0.f;
        }
#pragma unroll
        for (int kt = 0; kt < 8; kt++) {
            int k16 = kw * 8 + kt;
            unsigned int a0, a1, a2, a3;
            ldsm_x4(a0, a1, a2, a3, aBase + k16 * 32);
#pragma unroll
            for (int nt = 0; nt < 3; nt++) {
                unsigned int b0, b1;
                ldsm_x2(b0, b1, bBase + (24 + nt * 8) * RSTRIDE_B + k16 * 32);
                mma16816(cC[nt], a0, a1, a2, a3, b0, b1);
            }
        }
        {
            int r0 = lane >> 2, c0 = (lane & 3) * 2;
            int bb = mw * 16 + r0;
#pragma unroll
            for (int nt = 0; nt < 3; nt++) {
                Gred[(kw * 32 + bb) * 24 + nt * 8 + c0]         = cC[nt][0];
                Gred[(kw * 32 + bb) * 24 + nt * 8 + c0 + 1]     = cC[nt][1];
                Gred[(kw * 32 + bb + 8) * 24 + nt * 8 + c0]     = cC[nt][2];
                Gred[(kw * 32 + bb + 8) * 24 + nt * 8 + c0 + 1] = cC[nt][3];
            }
        }
        __syncthreads();
        if (tid < 256) {
            float cr = 0.f, cz = 0.f, cn = 0.f;
#pragma unroll
            for (int k = 0; k < 8; k++) {
                int base2 = (k * 32 + b) * 24;
                cr += Gred[base2 + jj];
                cz += Gred[base2 + 8 + jj];
                cn += Gred[base2 + 16 + jj];
            }
            int row = s * BATCH + b;
            int j = j0 + jj;
            const float* xg = g_dec_xg + (size_t)row * G3;
            float xr = __ldg(xg + j) + cr;
            float xz = __ldg(xg + 1024 + j) + cz;
            float xn = __ldg(xg + 2048 + j) + cn;
            float hprev = g_hbuf[hb][b * HID + j];
            float r = 1.f / (1.f + expf(-(xr + hr + br)));
            float z = 1.f / (1.f + expf(-(xz + hz + bz)));
            float n = tanhf(xn + r * (hn + bn_));
            float hnew = (1.f - z) * n + z * hprev;
            g_hbuf[hb ^ 1][b * HID + j] = hnew;
            __nv_bfloat16 h16 = __float2bfloat16(hnew);
            g_hbuf_bf[hb ^ 1][b * HID + j] = h16;
            g_dech_bf[(size_t)row * HID + j] = h16;
        }
        grid_sync();
    }
}

// ------------------------------- loss ------------------------------------
__global__ void __launch_bounds__(256) loss_combine(const int* __restrict__ tlen)
{
    int w = threadIdx.x >> 5, lane = threadIdx.x & 31;
    int row = blockIdx.x * 8 + w;
    float m = -3.4e38f, s = 0.f;
    for (int i = lane; i < LNB; i += 32) {
        float2 p = g_part[(size_t)row * LNB + i];
        float M = fmaxf(m, p.x);
        s = s * __expf(m - M) + p.y * __expf(p.x - M);
        m = M;
    }
#pragma unroll
    for (int o = 16; o; o >>= 1) {
        float mo = __shfl_xor_sync(0xffffffffu, m, o);
        float so = __shfl_xor_sync(0xffffffffu, s, o);
        float M = fmaxf(m, mo);
        s = s * __expf(m - M) + so * __expf(mo - M);
        m = M;
    }
    if (lane == 0) {
        int sp = row >> 5, b = row & 31;
        float lp = g_tgtlog[row] - m - logf(s);
        g_tok_lp[row] = (sp < tlen[b]) ? lp : 0.f;
    }
}

__global__ void __launch_bounds__(256) loss_final(const int* __restrict__ tlen,
                                                  float* __restrict__ out)
{
    __shared__ float red[256];
    int tid = threadIdx.x;
    float ssum = 0.f;
    for (int r = tid; r < ROWS; r += 256) ssum += g_tok_lp[r];
    red[tid] = ssum; __syncthreads();
    for (int o = 128; o; o >>= 1) {
        if (tid < o) red[tid] += red[tid + o];
        __syncthreads();
    }
    if (tid == 0) {
        float cnt = 0.f;
        for (int b = 0; b < BATCH; b++) cnt += (float)tlen[b];
        out[0] = -red[0] / cnt;
    }
}

// ------------------------------- launch ----------------------------------
extern "C" void kernel_launch(void* const* d_in, const int* in_sizes, int n_in,
                              void* d_out, int out_size)
{
    const int* s         = (const int*)d_in[0];
    const int* t         = (const int*)d_in[1];
    const int* tlen      = (const int*)d_in[2];
    const float* emb     = (const float*)d_in[3];
    const float* enc_Wih = (const float*)d_in[4];
    const float* enc_Whh = (const float*)d_in[5];
    const float* enc_bih = (const float*)d_in[6];
    const float* enc_bhh = (const float*)d_in[7];
    const float* dec_Wih = (const float*)d_in[8];
    const float* dec_Whh = (const float*)d_in[9];
    const float* dec_Wch = (const float*)d_in[10];
    const float* dec_bih = (const float*)d_in[11];
    const float* dec_bhh = (const float*)d_in[12];
    const float* attn_W  = (const float*)d_in[13];
    const float* attn_v  = (const float*)d_in[14];
    const float* Wout    = (const float*)d_in[15];
    const float* bout    = (const float*)d_in[16];
    float* out = (float*)d_out;

    cudaFuncSetAttribute((const void*)enc_scan,
                         cudaFuncAttributeMaxDynamicSharedMemorySize, ENC_SM_TOTAL);
    cudaFuncSetAttribute((const void*)dec_scan,
                         cudaFuncAttributeMaxDynamicSharedMemorySize, DEC_SM_TOTAL);

    build_gather<<<8, 256>>>(s, t);
    conv_emb<<<(2 * ROWS * EMB / 8 + 255) / 256, 256>>>(emb);
    conv_all<<<(int)((CVEND / 8 + 255) / 256), 256>>>(enc_Wih, dec_Wih, Wout,
                                                      enc_Whh, dec_Whh, dec_Wch);
    conv_attnW<<<HID * HID / 256, 256>>>(attn_W);

    hgemm<<<dim3(G3 / 128, ROWS / 128), 256>>>(0, enc_bih);
    hgemm<<<dim3(G3 / 128, ROWS / 128), 256>>>(1, dec_bih);
    enc_scan<<<NBLK, SNTHR, ENC_SM_TOTAL>>>(enc_bhh);
    hgemm<<<dim3(HID / 128, ROWS / 128), 256>>>(2, (const float*)0);
    dec_scan<<<NBLK, SNTHR, DEC_SM_TOTAL>>>(dec_bhh, attn_v);
    hgemm<<<dim3(VOC / 128, ROWS / 128), 256>>>(3, bout);
    loss_combine<<<ROWS / 8, 256>>>(tlen);
    loss_final<<<1, 256>>>(tlen, out);
}

// round 14
// speedup vs baseline: 1.0021x; 1.0021x over previous
#include <cuda_runtime.h>
#include <cuda_bf16.h>
#include <cstdint>
#include <cstddef>
#include <math.h>

#define BATCH 32
#define SEQ   64
#define HID   1024
#define EMB   512
#define VOC   32000
#define G3    3072
#define ROWS  2048   // SEQ*BATCH
#define LNB   250    // VOC/128 logits col-blocks

#define NBLK  128    // persistent scan blocks (HID/8)
#define SNTHR 512    // 16 warps

// padded smem row stride for bf16 weight/activation tiles: 1024 + 8 elems
#define RSTRIDE 1032           // elements
#define RSTRIDE_B 2064         // bytes

// enc smem carve
#define ENC_W_BYTES   (24 * RSTRIDE_B)
#define ENC_HS_OFF    ENC_W_BYTES
#define ENC_GRED_OFF  (ENC_HS_OFF + 32 * RSTRIDE_B)
#define ENC_SM_TOTAL  (ENC_GRED_OFF + 8 * 32 * 24 * 4)

// dec smem carve
#define DEC_W_BYTES   (56 * RSTRIDE_B)
#define DEC_HS_OFF    DEC_W_BYTES
#define DEC_GRED_OFF  (DEC_HS_OFF + 32 * RSTRIDE_B)
#define DEC_WHRED_OFF (DEC_GRED_OFF + 8 * 32 * 24 * 4)
#define DEC_SSC_OFF   (DEC_WHRED_OFF + 8 * 32 * 8 * 4)
#define DEC_SM_TOTAL  (DEC_SSC_OFF + SEQ * 4)

// hgemm 3-stage dynamic smem carve
#define PADK 40
#define HG_STG (128 * PADK * 2)          // 10240 B per stage per operand
#define HG_B_OFF (3 * HG_STG)            // 30720
#define HG_SM_TOTAL (6 * HG_STG)         // 61440

// ------------------------------ scratch ---------------------------------
__device__ float g_enc_xg[ROWS * G3];
__device__ float g_dec_xg[ROWS * G3];
__device__ float g_enc_outs[ROWS * HID];
__device__ float g_enc_energy[ROWS * HID];
__device__ float g_hbuf[2][BATCH * HID];
__device__ float g_wh[BATCH * HID];
__device__ float g_scores[BATCH * SEQ];
__device__ float g_tok_lp[ROWS];
__device__ float g_tgtlog[ROWS];
__device__ int   g_gidx_enc[ROWS];
__device__ int   g_gidx_dec[ROWS];
__device__ int   g_tgtcol[ROWS];
__device__ __align__(16) float2 g_part[(size_t)ROWS * LNB];
__device__ unsigned g_bar_arrive = 0;
__device__ volatile unsigned g_bar_phase = 0;
__device__ volatile unsigned g_sbar[BATCH];

// bf16 operands
__device__ __align__(16) __nv_bfloat16 g_encA_bf[ROWS * EMB];
__device__ __align__(16) __nv_bfloat16 g_decA_bf[ROWS * EMB];
__device__ __align__(16) __nv_bfloat16 g_encWih_bf[G3 * EMB];
__device__ __align__(16) __nv_bfloat16 g_decWih_bf[G3 * EMB];
__device__ __align__(16) __nv_bfloat16 g_We_bf[HID * HID];
__device__ __align__(16) __nv_bfloat16 g_Wh_bf[HID * HID];
__device__ __align__(16) __nv_bfloat16 g_Wout_bf[(size_t)VOC * HID];
__device__ __align__(16) __nv_bfloat16 g_encouts_bf[ROWS * HID];
__device__ __align__(16) __nv_bfloat16 g_dech_bf[ROWS * HID];
__device__ __align__(16) __nv_bfloat16 g_encWhh_bf[G3 * HID];
__device__ __align__(16) __nv_bfloat16 g_decWhh_bf[G3 * HID];
__device__ __align__(16) __nv_bfloat16 g_decWch_bf[G3 * HID];
__device__ __align__(16) __nv_bfloat16 g_hbuf_bf[2][BATCH * HID];
__device__ __align__(16) __nv_bfloat16 g_ctx_bf[BATCH * HID];

// ------------------------------ helpers ---------------------------------
__device__ __forceinline__ float tanh_approx(float x) {
    float y; asm("tanh.approx.f32 %0, %1;" : "=f"(y) : "f"(x)); return y;
}

// R12-proven atomic barrier: release by last arriver, single counter.
__device__ __forceinline__ void grid_sync() {
    __syncthreads();
    if (threadIdx.x == 0) {
        __threadfence();
        unsigned ph = g_bar_phase;
        unsigned a = atomicAdd(&g_bar_arrive, 1u);
        if (a == (unsigned)(NBLK - 1)) {
            g_bar_arrive = 0u;
            __threadfence();
            g_bar_phase = ph + 1u;
        } else {
            while (g_bar_phase == ph) { __nanosleep(32); }
        }
    }
    __syncthreads();
}

__device__ __forceinline__ void group_sync4(int b2, unsigned target) {
    __syncthreads();
    if (threadIdx.x == 0) {
        __threadfence();
        atomicAdd((unsigned*)&g_sbar[b2], 1u);
        while (g_sbar[b2] < target) { }
        __threadfence();
    }
    __syncthreads();
}

__device__ __forceinline__ unsigned int smem_u32(const void* p) {
    return (unsigned int)__cvta_generic_to_shared(p);
}
__device__ __forceinline__ void cp16(unsigned int dst, const void* src, bool pred) {
    int sz = pred ? 16 : 0;
    asm volatile("cp.async.cg.shared.global [%0], [%1], 16, %2;\n"
                 :: "r"(dst), "l"(src), "r"(sz));
}
__device__ __forceinline__ void cp_commit() { asm volatile("cp.async.commit_group;\n"); }
__device__ __forceinline__ void cp_wait0()  { asm volatile("cp.async.wait_group 0;\n"); }
__device__ __forceinline__ void cp_wait1()  { asm volatile("cp.async.wait_group 1;\n"); }
__device__ __forceinline__ void ldsm_x4(unsigned int& r0, unsigned int& r1,
                                        unsigned int& r2, unsigned int& r3, unsigned int a) {
    asm volatile("ldmatrix.sync.aligned.m8n8.x4.shared.b16 {%0,%1,%2,%3},[%4];"
                 : "=r"(r0), "=r"(r1), "=r"(r2), "=r"(r3) : "r"(a));
}
__device__ __forceinline__ void ldsm_x2(unsigned int& r0, unsigned int& r1, unsigned int a) {
    asm volatile("ldmatrix.sync.aligned.m8n8.x2.shared.b16 {%0,%1},[%2];"
                 : "=r"(r0), "=r"(r1) : "r"(a));
}
__device__ __forceinline__ void mma16816(float* c, unsigned int a0, unsigned int a1,
                                         unsigned int a2, unsigned int a3,
                                         unsigned int b0, unsigned int b1) {
    asm volatile("mma.sync.aligned.m16n8k16.row.col.f32.bf16.bf16.f32 "
                 "{%0,%1,%2,%3},{%4,%5,%6,%7},{%8,%9},{%0,%1,%2,%3};"
                 : "+f"(c[0]), "+f"(c[1]), "+f"(c[2]), "+f"(c[3])
                 : "r"(a0), "r"(a1), "r"(a2), "r"(a3), "r"(b0), "r"(b1));
}

// --------------------------- gather indices -----------------------------
__global__ void build_gather(const int* __restrict__ s, const int* __restrict__ t) {
    int r = blockIdx.x * blockDim.x + threadIdx.x;
    if (blockIdx.x == 0 && threadIdx.x < BATCH) g_sbar[threadIdx.x] = 0u;
    if (r >= ROWS) return;
    int sp = r >> 5, b = r & 31;
    g_gidx_enc[r] = s[b * SEQ + sp];
    g_gidx_dec[r] = (sp == 0) ? -1 : t[b * SEQ + sp - 1];
    g_tgtcol[r] = t[b * SEQ + sp];
}

// ------------------- gathered embedding rows -> bf16 ---------------------
__global__ void __launch_bounds__(256) conv_emb(const float* __restrict__ emb) {
    long long e = ((long long)blockIdx.x * blockDim.x + threadIdx.x) * 8;
    if (e >= 2LL * ROWS * EMB) return;
    int which = (e >= (long long)ROWS * EMB);
    long long off = e - (long long)which * ROWS * EMB;
    int r = (int)(off >> 9);
    int c = (int)(off & (EMB - 1));
    int idx = which ? g_gidx_dec[r] : g_gidx_enc[r];
    __nv_bfloat16* dst = which ? g_decA_bf : g_encA_bf;
    __nv_bfloat16 o[8];
    if (idx < 0) {
#pragma unroll
        for (int k = 0; k < 8; k++) o[k] = __float2bfloat16(0.f);
    } else {
        const float* src = emb + (size_t)idx * EMB + c;
        float4 v0 = *(const float4*)src;
        float4 v1 = *(const float4*)(src + 4);
        o[0] = __float2bfloat16(v0.x); o[1] = __float2bfloat16(v0.y);
        o[2] = __float2bfloat16(v0.z); o[3] = __float2bfloat16(v0.w);
        o[4] = __float2bfloat16(v1.x); o[5] = __float2bfloat16(v1.y);
        o[6] = __float2bfloat16(v1.z); o[7] = __float2bfloat16(v1.w);
    }
    *(uint4*)(dst + off) = *(const uint4*)o;
}

// ---------------------------- fp32 -> bf16 (weights) ---------------------
#define CVO1 (G3 * EMB)
#define CVO2 (CVO1 + G3 * EMB)
#define CVO3 (CVO2 + VOC * HID)
#define CVO4 (CVO3 + G3 * HID)
#define CVO5 (CVO4 + G3 * HID)
#define CVEND (CVO5 + G3 * HID)
__global__ void __launch_bounds__(256) conv_all(
    const float* __restrict__ eWih, const float* __restrict__ dWih,
    const float* __restrict__ Wout, const float* __restrict__ eWhh,
    const float* __restrict__ dWhh, const float* __restrict__ dWch)
{
    long long e = ((long long)blockIdx.x * blockDim.x + threadIdx.x) * 8;
    if (e >= CVEND) return;
    const float* src;
    __nv_bfloat16* dst;
    long long off;
    if (e < CVO1)      { src = eWih; dst = g_encWih_bf; off = e; }
    else if (e < CVO2) { src = dWih; dst = g_decWih_bf; off = e - CVO1; }
    else if (e < CVO3) { src = Wout; dst = g_Wout_bf;   off = e - CVO2; }
    else if (e < CVO4) { src = eWhh; dst = g_encWhh_bf; off = e - CVO3; }
    else if (e < CVO5) { src = dWhh; dst = g_decWhh_bf; off = e - CVO4; }
    else               { src = dWch; dst = g_decWch_bf; off = e - CVO5; }
    float4 v0 = *(const float4*)(src + off);
    float4 v1 = *(const float4*)(src + off + 4);
    __nv_bfloat16 o[8];
    o[0] = __float2bfloat16(v0.x); o[1] = __float2bfloat16(v0.y);
    o[2] = __float2bfloat16(v0.z); o[3] = __float2bfloat16(v0.w);
    o[4] = __float2bfloat16(v1.x); o[5] = __float2bfloat16(v1.y);
    o[6] = __float2bfloat16(v1.z); o[7] = __float2bfloat16(v1.w);
    *(uint4*)(dst + off) = *(const uint4*)o;
}

__global__ void conv_attnW(const float* __restrict__ attn_W) {
    int i = blockIdx.x * blockDim.x + threadIdx.x;
    if (i < HID * HID) {
        int j = i >> 10;
        int k = i & 1023;
        g_We_bf[i] = __float2bfloat16(attn_W[(size_t)j * 2048 + 1024 + k]);
        g_Wh_bf[i] = __float2bfloat16(attn_W[(size_t)j * 2048 + k]);
    }
}

// ---------------------------- bf16 HMMA GEMM (3-stage pipeline) ----------
__global__ void __launch_bounds__(256) hgemm(int which, const float* __restrict__ bias)
{
    extern __shared__ char sm[];
    unsigned int smb = smem_u32(sm);

    const __nv_bfloat16* A;
    const __nv_bfloat16* Wb;
    float* C;
    int N, K;
    if (which == 0) {
        A = g_encA_bf; Wb = g_encWih_bf; C = g_enc_xg; N = G3; K = EMB;
    } else if (which == 1) {
        A = g_decA_bf; Wb = g_decWih_bf; C = g_dec_xg; N = G3; K = EMB;
    } else if (which == 2) {
        A = g_encouts_bf; Wb = g_We_bf; C = g_enc_energy; N = HID; K = HID;
    } else {
        A = g_dech_bf; Wb = g_Wout_bf; C = (float*)0; N = VOC; K = HID;
    }

    int tid = threadIdx.x;
    int bn = blockIdx.x, bm = blockIdx.y;
    int warp = tid >> 5, lane = tid & 31;
    int wm = warp >> 2, wn = warp & 3;

    int lr = tid >> 2;
    int lc = (tid & 3) * 8;

    const __nv_bfloat16* a0 = A + (size_t)(bm * 128 + lr) * K;
    const __nv_bfloat16* a1 = A + (size_t)(bm * 128 + lr + 64) * K;
    const __nv_bfloat16* b0p = Wb + (size_t)(bn * 128 + lr) * K;
    const __nv_bfloat16* b1p = Wb + (size_t)(bn * 128 + lr + 64) * K;

    // per-stage store addresses (stage 0 base)
    unsigned int sa0 = smb + (unsigned)((lr * PADK + lc) * 2);
    unsigned int sa1 = smb + (unsigned)(((lr + 64) * PADK + lc) * 2);
    unsigned int sb0 = smb + HG_B_OFF + (unsigned)((lr * PADK + lc) * 2);
    unsigned int sb1 = smb + HG_B_OFF + (unsigned)(((lr + 64) * PADK + lc) * 2);

    float acc[4][4][4];
#pragma unroll
    for (int mi = 0; mi < 4; mi++) {
#pragma unroll
        for (int ni = 0; ni < 4; ni++) {
#pragma unroll
            for (int q = 0; q < 4; q++) acc[mi][ni][q] = 0.f;
        }
    }

    // ldsm base offsets (within a stage)
    unsigned int aoff = (unsigned)(((wm * 64 + (lane & 15)) * PADK + (lane >> 4) * 8) * 2);
    unsigned int boff = (unsigned)(((wn * 32 + (lane & 7)) * PADK + ((lane >> 3) & 1) * 8) * 2) + HG_B_OFF;

    int KT = K / 32;
    // prologue: tiles 0 and 1
#pragma unroll
    for (int p = 0; p < 2; p++) {
        unsigned int so = (unsigned)p * HG_STG;
        int k = p * 32;
        cp16(sa0 + so, a0 + k + lc, true);
        cp16(sa1 + so, a1 + k + lc, true);
        cp16(sb0 + so, b0p + k + lc, true);
        cp16(sb1 + so, b1p + k + lc, true);
        cp_commit();
    }

    int stage = 0;
    for (int kt = 0; kt < KT; kt++) {
        if (kt == KT - 1) cp_wait0(); else cp_wait1();
        __syncthreads();
        if (kt + 2 < KT) {
            int k = (kt + 2) * 32;
            int nst = (stage + 2) % 3;
            unsigned int so = (unsigned)nst * HG_STG;
            cp16(sa0 + so, a0 + k + lc, true);
            cp16(sa1 + so, a1 + k + lc, true);
            cp16(sb0 + so, b0p + k + lc, true);
            cp16(sb1 + so, b1p + k + lc, true);
            cp_commit();
        }
        unsigned int sbase = smb + (unsigned)stage * HG_STG;
#pragma unroll
        for (int ks = 0; ks < 32; ks += 16) {
            unsigned int af[4][4];
#pragma unroll
            for (int mi = 0; mi < 4; mi++) {
                unsigned int addr = sbase + aoff + (unsigned)((mi * 16 * PADK + ks) * 2);
                ldsm_x4(af[mi][0], af[mi][1], af[mi][2], af[mi][3], addr);
            }
            unsigned int bfr[4][2];
#pragma unroll
            for (int ni = 0; ni < 4; ni++) {
                unsigned int addr = sbase + boff + (unsigned)((ni * 8 * PADK + ks) * 2);
                ldsm_x2(bfr[ni][0], bfr[ni][1], addr);
            }
#pragma unroll
            for (int mi = 0; mi < 4; mi++) {
#pragma unroll
                for (int ni = 0; ni < 4; ni++) {
                    mma16816(acc[mi][ni], af[mi][0], af[mi][1], af[mi][2], af[mi][3],
                             bfr[ni][0], bfr[ni][1]);
                }
            }
        }
        stage = (stage + 1) % 3;
        __syncthreads();   // protect stage reuse (stage we just read is 2 iters away from rewrite)
    }

    int row_base = bm * 128 + wm * 64;
    int col_base = bn * 128 + wn * 32;

    if (which == 3) {
        float* pm = (float*)sm;
        float* ps = pm + 512;
        float bb2[4][2];
#pragma unroll
        for (int ni = 0; ni < 4; ni++) {
            int c0 = col_base + ni * 8 + (lane & 3) * 2;
            bb2[ni][0] = __ldg(bias + c0);
            bb2[ni][1] = __ldg(bias + c0 + 1);
        }
        __syncthreads();
#pragma unroll
        for (int mi = 0; mi < 4; mi++) {
#pragma unroll
            for (int h = 0; h < 2; h++) {
                int rloc = wm * 64 + mi * 16 + (lane >> 2) + 8 * h;
                int grow = bm * 128 + rloc;
                int tc = g_tgtcol[grow] - bn * 128;
                float v[8];
                float m = -3.4e38f;
#pragma unroll
                for (int ni = 0; ni < 4; ni++) {
#pragma unroll
                    for (int q = 0; q < 2; q++) {
                        float x = acc[mi][ni][2 * h + q] + bb2[ni][q];
                        v[ni * 2 + q] = x;
                        m = fmaxf(m, x);
                        int cl = wn * 32 + ni * 8 + (lane & 3) * 2 + q;
                        if (cl == tc) g_tgtlog[grow] = x;
                    }
                }
                float ssum = 0.f;
#pragma unroll
                for (int k2 = 0; k2 < 8; k2++) ssum += __expf(v[k2] - m);
#pragma unroll
                for (int off = 1; off <= 2; off <<= 1) {
                    float mo = __shfl_xor_sync(0xffffffffu, m, off);
                    float so = __shfl_xor_sync(0xffffffffu, ssum, off);
                    float M = fmaxf(m, mo);
                    ssum = ssum * __expf(m - M) + so * __expf(mo - M);
                    m = M;
                }
                if ((lane & 3) == 0) { pm[rloc * 4 + wn] = m; ps[rloc * 4 + wn] = ssum; }
            }
        }
        __syncthreads();
        if (tid < 128) {
            float m = pm[tid * 4], s2 = ps[tid * 4];
#pragma unroll
            for (int w2 = 1; w2 < 4; w2++) {
                float mo = pm[tid * 4 + w2], so = ps[tid * 4 + w2];
                float M = fmaxf(m, mo);
                s2 = s2 * __expf(m - M) + so * __expf(mo - M);
                m = M;
            }
            g_part[(size_t)(bm * 128 + tid) * LNB + bn] = make_float2(m, s2);
        }
        return;
    }

#pragma unroll
    for (int mi = 0; mi < 4; mi++) {
#pragma unroll
        for (int ni = 0; ni < 4; ni++) {
            int r0 = row_base + mi * 16 + (lane >> 2);
            int c0 = col_base + ni * 8 + (lane & 3) * 2;
            float bv0 = bias ? __ldg(bias + c0) : 0.f;
            float bv1 = bias ? __ldg(bias + c0 + 1) : 0.f;
            float2 v0 = make_float2(acc[mi][ni][0] + bv0, acc[mi][ni][1] + bv1);
            float2 v1 = make_float2(acc[mi][ni][2] + bv0, acc[mi][ni][3] + bv1);
            *(float2*)(C + (size_t)r0 * N + c0) = v0;
            *(float2*)(C + (size_t)(r0 + 8) * N + c0) = v1;
        }
    }
}

// ---------------------------- encoder scan (HMMA) ------------------------
__global__ void __launch_bounds__(SNTHR) enc_scan(const float* __restrict__ bhh)
{
    extern __shared__ char sm[];
    __nv_bfloat16* Wsm = (__nv_bfloat16*)sm;
    __nv_bfloat16* hs  = (__nv_bfloat16*)(sm + ENC_HS_OFF);
    float* Gred        = (float*)(sm + ENC_GRED_OFF);

    int tid = threadIdx.x;
    int w = tid >> 5, lane = tid & 31;
    int mw = w & 1, kw = w >> 1;
    int j0 = blockIdx.x * 8;

    for (int f = tid; f < 24 * 128; f += SNTHR) {
        int r = f >> 7, c = f & 127;
        int grow = (r < 8) ? (j0 + r) : (r < 16) ? (1024 + j0 + r - 8) : (2048 + j0 + r - 16);
        cp16(smem_u32(Wsm + r * RSTRIDE + c * 8), g_encWhh_bf + (size_t)grow * HID + c * 8, true);
    }
    cp_commit();
    for (int i = blockIdx.x * SNTHR + tid; i < BATCH * HID; i += NBLK * SNTHR) {
        g_hbuf[0][i] = 0.f;
        g_hbuf_bf[0][i] = __float2bfloat16(0.f);
    }
    cp_wait0();
    __syncthreads();
    grid_sync();

    int jj = tid & 7, b = tid >> 3;
    float br = 0.f, bz = 0.f, bn_ = 0.f;
    if (tid < 256) {
        br = bhh[j0 + jj]; bz = bhh[1024 + j0 + jj]; bn_ = bhh[2048 + j0 + jj];
    }

    unsigned int aBase = smem_u32(hs) + (unsigned)((mw * 16 + (lane & 15)) * RSTRIDE_B + ((lane >> 4) * 8) * 2);
    unsigned int bBase = smem_u32(Wsm) + (unsigned)((lane & 7) * RSTRIDE_B + (((lane >> 3) & 1) * 8) * 2);

    for (int s = 0; s < SEQ; s++) {
        int hb = s & 1;
        for (int f = tid; f < 32 * 128; f += SNTHR) {
            int r = f >> 7, c = f & 127;
            cp16(smem_u32(hs + r * RSTRIDE + c * 8), g_hbuf_bf[hb] + r * HID + c * 8, true);
        }
        cp_commit(); cp_wait0(); __syncthreads();

        float cG[3][4];
#pragma unroll
        for (int nt = 0; nt < 3; nt++) {
#pragma unroll
            for (int q = 0; q < 4; q++) cG[nt][q] = 0.f;
        }
#pragma unroll
        for (int kt = 0; kt < 8; kt++) {
            int k16 = kw * 8 + kt;
            unsigned int a0, a1, a2, a3;
            ldsm_x4(a0, a1, a2, a3, aBase + k16 * 32);
#pragma unroll
            for (int nt = 0; nt < 3; nt++) {
                unsigned int b0, b1;
                ldsm_x2(b0, b1, bBase + nt * 8 * RSTRIDE_B + k16 * 32);
                mma16816(cG[nt], a0, a1, a2, a3, b0, b1);
            }
        }
        {
            int r0 = lane >> 2, c0 = (lane & 3) * 2;
            int bb = mw * 16 + r0;
#pragma unroll
            for (int nt = 0; nt < 3; nt++) {
                Gred[(kw * 32 + bb) * 24 + nt * 8 + c0]         = cG[nt][0];
                Gred[(kw * 32 + bb) * 24 + nt * 8 + c0 + 1]     = cG[nt][1];
                Gred[(kw * 32 + bb + 8) * 24 + nt * 8 + c0]     = cG[nt][2];
                Gred[(kw * 32 + bb + 8) * 24 + nt * 8 + c0 + 1] = cG[nt][3];
            }
        }
        __syncthreads();
        if (tid < 256) {
            float hr = 0.f, hz = 0.f, hn = 0.f;
#pragma unroll
            for (int k = 0; k < 8; k++) {
                int base2 = (k * 32 + b) * 24;
                hr += Gred[base2 + jj];
                hz += Gred[base2 + 8 + jj];
                hn += Gred[base2 + 16 + jj];
            }
            int row = s * BATCH + b;
            int j = j0 + jj;
            const float* xg = g_enc_xg + (size_t)row * G3;
            float xr = __ldg(xg + j), xz = __ldg(xg + 1024 + j), xn = __ldg(xg + 2048 + j);
            float hprev = g_hbuf[hb][b * HID + j];
            float r = 1.f / (1.f + expf(-(xr + hr + br)));
            float z = 1.f / (1.f + expf(-(xz + hz + bz)));
            float n = tanhf(xn + r * (hn + bn_));
            float hnew = (1.f - z) * n + z * hprev;
            g_hbuf[hb ^ 1][b * HID + j] = hnew;
            __nv_bfloat16 h16 = __float2bfloat16(hnew);
            g_hbuf_bf[hb ^ 1][b * HID + j] = h16;
            g_enc_outs[(size_t)row * HID + j] = hnew;
            g_encouts_bf[(size_t)row * HID + j] = h16;
        }
        grid_sync();
    }
}

// ---------------------------- decoder scan (HMMA) ------------------------
__global__ void __launch_bounds__(SNTHR) dec_scan(const float* __restrict__ bhh,
                                                  const float* __restrict__ attn_v)
{
    extern __shared__ char sm[];
    __nv_bfloat16* Wsm = (__nv_bfloat16*)sm;
    __nv_bfloat16* hs  = (__nv_bfloat16*)(sm + DEC_HS_OFF);
    float* Gred        = (float*)(sm + DEC_GRED_OFF);
    float* whred       = (float*)(sm + DEC_WHRED_OFF);
    float* s_sc        = (float*)(sm + DEC_SSC_OFF);

    int tid = threadIdx.x;
    int w = tid >> 5, lane = tid & 31;
    int mw = w & 1, kw = w >> 1;
    int j0 = blockIdx.x * 8;

    for (int f = tid; f < 56 * 128; f += SNTHR) {
        int r = f >> 7, c = f & 127;
        const __nv_bfloat16* src;
        if (r < 24) {
            int grow = (r < 8) ? (j0 + r) : (r < 16) ? (1024 + j0 + r - 8) : (2048 + j0 + r - 16);
            src = g_decWhh_bf + (size_t)grow * HID;
        } else if (r < 48) {
            int rr = r - 24;
            int grow = (rr < 8) ? (j0 + rr) : (rr < 16) ? (1024 + j0 + rr - 8) : (2048 + j0 + rr - 16);
            src = g_decWch_bf + (size_t)grow * HID;
        } else {
            src = g_Wh_bf + (size_t)(j0 + r - 48) * HID;
        }
        cp16(smem_u32(Wsm + r * RSTRIDE + c * 8), src + c * 8, true);
    }
    cp_commit(); cp_wait0(); __syncthreads();
    grid_sync();

    int jj = tid & 7, b = tid >> 3;
    float br = 0.f, bz = 0.f, bn_ = 0.f;
    if (tid < 256) {
        br = bhh[j0 + jj]; bz = bhh[1024 + j0 + jj]; bn_ = bhh[2048 + j0 + jj];
    }

    unsigned int aBase = smem_u32(hs) + (unsigned)((mw * 16 + (lane & 15)) * RSTRIDE_B + ((lane >> 4) * 8) * 2);
    unsigned int bBase = smem_u32(Wsm) + (unsigned)((lane & 7) * RSTRIDE_B + (((lane >> 3) & 1) * 8) * 2);

    float hr = 0.f, hz = 0.f, hn = 0.f;
    int b2 = blockIdx.x & 31;

    for (int s = 0; s < SEQ; s++) {
        int hb = s & 1;

        for (int f = tid; f < 32 * 128; f += SNTHR) {
            int r = f >> 7, c = f & 127;
            cp16(smem_u32(hs + r * RSTRIDE + c * 8), g_hbuf_bf[hb] + r * HID + c * 8, true);
        }
        cp_commit(); cp_wait0(); __syncthreads();

        float cG[3][4], cW[4];
#pragma unroll
        for (int nt = 0; nt < 3; nt++) {
#pragma unroll
            for (int q = 0; q < 4; q++) cG[nt][q] = 0.f;
        }
#pragma unroll
        for (int q = 0; q < 4; q++) cW[q] = 0.f;
#pragma unroll
        for (int kt = 0; kt < 8; kt++) {
            int k16 = kw * 8 + kt;
            unsigned int a0, a1, a2, a3;
            ldsm_x4(a0, a1, a2, a3, aBase + k16 * 32);
#pragma unroll
            for (int nt = 0; nt < 3; nt++) {
                unsigned int b0, b1;
                ldsm_x2(b0, b1, bBase + nt * 8 * RSTRIDE_B + k16 * 32);
                mma16816(cG[nt], a0, a1, a2, a3, b0, b1);
            }
            unsigned int b0, b1;
            ldsm_x2(b0, b1, bBase + 48 * RSTRIDE_B + k16 * 32);
            mma16816(cW, a0, a1, a2, a3, b0, b1);
        }
        {
            int r0 = lane >> 2, c0 = (lane & 3) * 2;
            int bb = mw * 16 + r0;
#pragma unroll
            for (int nt = 0; nt < 3; nt++) {
                Gred[(kw * 32 + bb) * 24 + nt * 8 + c0]         = cG[nt][0];
                Gred[(kw * 32 + bb) * 24 + nt * 8 + c0 + 1]     = cG[nt][1];
                Gred[(kw * 32 + bb + 8) * 24 + nt * 8 + c0]     = cG[nt][2];
                Gred[(kw * 32 + bb + 8) * 24 + nt * 8 + c0 + 1] = cG[nt][3];
            }
            whred[(kw * 32 + bb) * 8 + c0]         = cW[0];
            whred[(kw * 32 + bb) * 8 + c0 + 1]     = cW[1];
            whred[(kw * 32 + bb + 8) * 8 + c0]     = cW[2];
            whred[(kw * 32 + bb + 8) * 8 + c0 + 1] = cW[3];
        }
        __syncthreads();
        if (tid < 256) {
            float whv = 0.f;
            hr = 0.f; hz = 0.f; hn = 0.f;
#pragma unroll
            for (int k = 0; k < 8; k++) {
                int base2 = k * 32 + b;
                whv += whred[base2 * 8 + jj];
                hr += Gred[base2 * 24 + jj];
                hz += Gred[base2 * 24 + 8 + jj];
                hn += Gred[base2 * 24 + 16 + jj];
            }
            g_wh[b * HID + j0 + jj] = whv;
        }
        grid_sync();

        {
            int sp = (blockIdx.x >> 5) * 16 + w;
            const float* ee = g_enc_energy + (size_t)(sp * BATCH + b2) * HID;
            const float* whp = g_wh + b2 * HID;
            float acc = 0.f;
            for (int k = lane; k < HID; k += 32)
                acc += tanh_approx(__ldg(ee + k) + __ldcg(whp + k)) * __ldg(attn_v + k);
#pragma unroll
            for (int o = 16; o; o >>= 1) acc += __shfl_xor_sync(0xffffffffu, acc, o);
            if (lane == 0) g_scores[b2 * SEQ + sp] = acc;
        }
        group_sync4(b2, 4u * (unsigned)(s + 1));

        {
            int jq = blockIdx.x >> 5;
            if (tid < SEQ) s_sc[tid] = __ldcg(g_scores + b2 * SEQ + tid);
            __syncthreads();
            if (w == 0) {
                float v0 = s_sc[lane], v1 = s_sc[lane + 32];
                float m = fmaxf(v0, v1);
#pragma unroll
                for (int o = 16; o; o >>= 1) m = fmaxf(m, __shfl_xor_sync(0xffffffffu, m, o));
                float e0 = expf(v0 - m), e1 = expf(v1 - m);
                float ssum = e0 + e1;
#pragma unroll
                for (int o = 16; o; o >>= 1) ssum += __shfl_xor_sync(0xffffffffu, ssum, o);
                float inv = 1.f / ssum;
                s_sc[lane] = e0 * inv; s_sc[lane + 32] = e1 * inv;
            }
            __syncthreads();
            if (tid < 256) {
                int jx = jq * 256 + tid;
                float a0 = 0.f, a1 = 0.f, a2 = 0.f, a3 = 0.f;
#pragma unroll 4
                for (int sp = 0; sp < SEQ; sp += 4) {
                    a0 += s_sc[sp]     * __ldg(g_enc_outs + (size_t)((sp)     * BATCH + b2) * HID + jx);
                    a1 += s_sc[sp + 1] * __ldg(g_enc_outs + (size_t)((sp + 1) * BATCH + b2) * HID + jx);
                    a2 += s_sc[sp + 2] * __ldg(g_enc_outs + (size_t)((sp + 2) * BATCH + b2) * HID + jx);
                    a3 += s_sc[sp + 3] * __ldg(g_enc_outs + (size_t)((sp + 3) * BATCH + b2) * HID + jx);
                }
                g_ctx_bf[b2 * HID + jx] = __float2bfloat16((a0 + a1) + (a2 + a3));
            }
        }
        grid_sync();

        for (int f = tid; f < 32 * 128; f += SNTHR) {
            int r = f >> 7, c = f & 127;
            cp16(smem_u32(hs + r * RSTRIDE + c * 8), g_ctx_bf + r * HID + c * 8, true);
        }
        cp_commit(); cp_wait0(); __syncthreads();

        float cC[3][4];
#pragma unroll
        for (int nt = 0; nt < 3; nt++) {
#pragma unroll
            for (int q = 0; q < 4; q++) cC[nt][q] = 0.f;
        }
#pragma unroll
        for (int kt = 0; kt < 8; kt++) {
            int k16 = kw * 8 + kt;
            unsigned int a0, a1, a2, a3;
            ldsm_x4(a0, a1, a2, a3, aBase + k16 * 32);
#pragma unroll
            for (int nt = 0; nt < 3; nt++) {
                unsigned int b0, b1;
                ldsm_x2(b0, b1, bBase + (24 + nt * 8) * RSTRIDE_B + k16 * 32);
                mma16816(cC[nt], a0, a1, a2, a3, b0, b1);
            }
        }
        {
            int r0 = lane >> 2, c0 = (lane & 3) * 2;
            int bb = mw * 16 + r0;
#pragma unroll
            for (int nt = 0; nt < 3; nt++) {
                Gred[(kw * 32 + bb) * 24 + nt * 8 + c0]         = cC[nt][0];
                Gred[(kw * 32 + bb) * 24 + nt * 8 + c0 + 1]     = cC[nt][1];
                Gred[(kw * 32 + bb + 8) * 24 + nt * 8 + c0]     = cC[nt][2];
                Gred[(kw * 32 + bb + 8) * 24 + nt * 8 + c0 + 1] = cC[nt][3];
            }
        }
        __syncthreads();
        if (tid < 256) {
            float cr = 0.f, cz = 0.f, cn = 0.f;
#pragma unroll
            for (int k = 0; k < 8; k++) {
                int base2 = (k * 32 + b) * 24;
                cr += Gred[base2 + jj];
                cz += Gred[base2 + 8 + jj];
                cn += Gred[base2 + 16 + jj];
            }
            int row = s * BATCH + b;
            int j = j0 + jj;
            const float* xg = g_dec_xg + (size_t)row * G3;
            float xr = __ldg(xg + j) + cr;
            float xz = __ldg(xg + 1024 + j) + cz;
            float xn = __ldg(xg + 2048 + j) + cn;
            float hprev = g_hbuf[hb][b * HID + j];
            float r = 1.f / (1.f + expf(-(xr + hr + br)));
            float z = 1.f / (1.f + expf(-(xz + hz + bz)));
            float n = tanhf(xn + r * (hn + bn_));
            float hnew = (1.f - z) * n + z * hprev;
            g_hbuf[hb ^ 1][b * HID + j] = hnew;
            __nv_bfloat16 h16 = __float2bfloat16(hnew);
            g_hbuf_bf[hb ^ 1][b * HID + j] = h16;
            g_dech_bf[(size_t)row * HID + j] = h16;
        }
        grid_sync();
    }
}

// ------------------------------- loss ------------------------------------
__global__ void __launch_bounds__(256) loss_combine(const int* __restrict__ tlen)
{
    int w = threadIdx.x >> 5, lane = threadIdx.x & 31;
    int row = blockIdx.x * 8 + w;
    float m = -3.4e38f, s = 0.f;
    for (int i = lane; i < LNB; i += 32) {
        float2 p = g_part[(size_t)row * LNB + i];
        float M = fmaxf(m, p.x);
        s = s * __expf(m - M) + p.y * __expf(p.x - M);
        m = M;
    }
#pragma unroll
    for (int o = 16; o; o >>= 1) {
        float mo = __shfl_xor_sync(0xffffffffu, m, o);
        float so = __shfl_xor_sync(0xffffffffu, s, o);
        float M = fmaxf(m, mo);
        s = s * __expf(m - M) + so * __expf(mo - M);
        m = M;
    }
    if (lane == 0) {
        int sp = row >> 5, b = row & 31;
        float lp = g_tgtlog[row] - m - logf(s);
        g_tok_lp[row] = (sp < tlen[b]) ? lp : 0.f;
    }
}

__global__ void __launch_bounds__(256) loss_final(const int* __restrict__ tlen,
                                                  float* __restrict__ out)
{
    __shared__ float red[256];
    int tid = threadIdx.x;
    float ssum = 0.f;
    for (int r = tid; r < ROWS; r += 256) ssum += g_tok_lp[r];
    red[tid] = ssum; __syncthreads();
    for (int o = 128; o; o >>= 1) {
        if (tid < o) red[tid] += red[tid + o];
        __syncthreads();
    }
    if (tid == 0) {
        float cnt = 0.f;
        for (int b = 0; b < BATCH; b++) cnt += (float)tlen[b];
        out[0] = -red[0] / cnt;
    }
}

// ------------------------------- launch ----------------------------------
extern "C" void kernel_launch(void* const* d_in, const int* in_sizes, int n_in,
                              void* d_out, int out_size)
{
    const int* s         = (const int*)d_in[0];
    const int* t         = (const int*)d_in[1];
    const int* tlen      = (const int*)d_in[2];
    const float* emb     = (const float*)d_in[3];
    const float* enc_Wih = (const float*)d_in[4];
    const float* enc_Whh = (const float*)d_in[5];
    const float* enc_bih = (const float*)d_in[6];
    const float* enc_bhh = (const float*)d_in[7];
    const float* dec_Wih = (const float*)d_in[8];
    const float* dec_Whh = (const float*)d_in[9];
    const float* dec_Wch = (const float*)d_in[10];
    const float* dec_bih = (const float*)d_in[11];
    const float* dec_bhh = (const float*)d_in[12];
    const float* attn_W  = (const float*)d_in[13];
    const float* attn_v  = (const float*)d_in[14];
    const float* Wout    = (const float*)d_in[15];
    const float* bout    = (const float*)d_in[16];
    float* out = (float*)d_out;

    cudaFuncSetAttribute((const void*)enc_scan,
                         cudaFuncAttributeMaxDynamicSharedMemorySize, ENC_SM_TOTAL);
    cudaFuncSetAttribute((const void*)dec_scan,
                         cudaFuncAttributeMaxDynamicSharedMemorySize, DEC_SM_TOTAL);
    cudaFuncSetAttribute((const void*)hgemm,
                         cudaFuncAttributeMaxDynamicSharedMemorySize, HG_SM_TOTAL);

    build_gather<<<8, 256>>>(s, t);
    conv_emb<<<(2 * ROWS * EMB / 8 + 255) / 256, 256>>>(emb);
    conv_all<<<(int)((CVEND / 8 + 255) / 256), 256>>>(enc_Wih, dec_Wih, Wout,
                                                      enc_Whh, dec_Whh, dec_Wch);
    conv_attnW<<<HID * HID / 256, 256>>>(attn_W);

    hgemm<<<dim3(G3 / 128, ROWS / 128), 256, HG_SM_TOTAL>>>(0, enc_bih);
    hgemm<<<dim3(G3 / 128, ROWS / 128), 256, HG_SM_TOTAL>>>(1, dec_bih);
    enc_scan<<<NBLK, SNTHR, ENC_SM_TOTAL>>>(enc_bhh);
    hgemm<<<dim3(HID / 128, ROWS / 128), 256, HG_SM_TOTAL>>>(2, (const float*)0);
    dec_scan<<<NBLK, SNTHR, DEC_SM_TOTAL>>>(dec_bhh, attn_v);
    hgemm<<<dim3(VOC / 128, ROWS / 128), 256, HG_SM_TOTAL>>>(3, bout);
    loss_combine<<<ROWS / 8, 256>>>(tlen);
    loss_final<<<1, 256>>>(tlen, out);
}

// round 15
// speedup vs baseline: 1.0104x; 1.0084x over previous
#include <cuda_runtime.h>
#include <cuda_bf16.h>
#include <cstdint>
#include <cstddef>
#include <math.h>

#define BATCH 32
#define SEQ   64
#define HID   1024
#define EMB   512
#define VOC   32000
#define G3    3072
#define ROWS  2048   // SEQ*BATCH
#define LNB   250    // VOC/128 logits col-blocks

#define NBLK  128    // persistent scan blocks (HID/8)
#define SNTHR 512    // 16 warps

// padded smem row stride for bf16 weight/activation tiles: 1024 + 8 elems
#define RSTRIDE 1032           // elements
#define RSTRIDE_B 2064         // bytes

// enc smem carve
#define ENC_W_BYTES   (24 * RSTRIDE_B)
#define ENC_HS_OFF    ENC_W_BYTES
#define ENC_GRED_OFF  (ENC_HS_OFF + 32 * RSTRIDE_B)
#define ENC_SM_TOTAL  (ENC_GRED_OFF + 8 * 32 * 24 * 4)

// dec smem carve
#define DEC_W_BYTES   (56 * RSTRIDE_B)
#define DEC_HS_OFF    DEC_W_BYTES
#define DEC_GRED_OFF  (DEC_HS_OFF + 32 * RSTRIDE_B)
#define DEC_WHRED_OFF (DEC_GRED_OFF + 8 * 32 * 24 * 4)
#define DEC_SSC_OFF   (DEC_WHRED_OFF + 8 * 32 * 8 * 4)
#define DEC_SM_TOTAL  (DEC_SSC_OFF + SEQ * 4)

// ------------------------------ scratch ---------------------------------
__device__ float g_enc_xg[ROWS * G3];
__device__ float g_dec_xg[ROWS * G3];
__device__ float g_enc_energy[ROWS * HID];
__device__ float g_hbuf[2][BATCH * HID];
__device__ float g_wh[BATCH * HID];
__device__ float g_scores[BATCH * SEQ];
__device__ float g_tok_lp[ROWS];
__device__ float g_tgtlog[ROWS];
__device__ int   g_gidx_enc[ROWS];
__device__ int   g_gidx_dec[ROWS];
__device__ int   g_tgtcol[ROWS];
__device__ __align__(16) float2 g_part[(size_t)ROWS * LNB];
__device__ unsigned g_bar_arrive = 0;
__device__ volatile unsigned g_bar_phase = 0;
__device__ volatile unsigned g_sbar[BATCH];

// bf16 operands
__device__ __align__(16) __nv_bfloat16 g_encA_bf[ROWS * EMB];
__device__ __align__(16) __nv_bfloat16 g_decA_bf[ROWS * EMB];
__device__ __align__(16) __nv_bfloat16 g_encWih_bf[G3 * EMB];
__device__ __align__(16) __nv_bfloat16 g_decWih_bf[G3 * EMB];
__device__ __align__(16) __nv_bfloat16 g_We_bf[HID * HID];
__device__ __align__(16) __nv_bfloat16 g_Wh_bf[HID * HID];
__device__ __align__(16) __nv_bfloat16 g_Wout_bf[(size_t)VOC * HID];
__device__ __align__(16) __nv_bfloat16 g_encouts_bf[ROWS * HID];
__device__ __align__(16) __nv_bfloat16 g_dech_bf[ROWS * HID];
__device__ __align__(16) __nv_bfloat16 g_encWhh_bf[G3 * HID];
__device__ __align__(16) __nv_bfloat16 g_decWhh_bf[G3 * HID];
__device__ __align__(16) __nv_bfloat16 g_decWch_bf[G3 * HID];
__device__ __align__(16) __nv_bfloat16 g_hbuf_bf[2][BATCH * HID];
__device__ __align__(16) __nv_bfloat16 g_ctx_bf[BATCH * HID];

// ------------------------------ helpers ---------------------------------
__device__ __forceinline__ float tanh_approx(float x) {
    float y; asm("tanh.approx.f32 %0, %1;" : "=f"(y) : "f"(x)); return y;
}

// R12-proven atomic barrier: release by last arriver, single counter.
__device__ __forceinline__ void grid_sync() {
    __syncthreads();
    if (threadIdx.x == 0) {
        __threadfence();
        unsigned ph = g_bar_phase;
        unsigned a = atomicAdd(&g_bar_arrive, 1u);
        if (a == (unsigned)(NBLK - 1)) {
            g_bar_arrive = 0u;
            __threadfence();
            g_bar_phase = ph + 1u;
        } else {
            while (g_bar_phase == ph) { __nanosleep(32); }
        }
    }
    __syncthreads();
}

__device__ __forceinline__ void group_sync4(int b2, unsigned target) {
    __syncthreads();
    if (threadIdx.x == 0) {
        __threadfence();
        atomicAdd((unsigned*)&g_sbar[b2], 1u);
        while (g_sbar[b2] < target) { }
        __threadfence();
    }
    __syncthreads();
}

__device__ __forceinline__ unsigned int smem_u32(const void* p) {
    return (unsigned int)__cvta_generic_to_shared(p);
}
__device__ __forceinline__ void cp16(unsigned int dst, const void* src, bool pred) {
    int sz = pred ? 16 : 0;
    asm volatile("cp.async.cg.shared.global [%0], [%1], 16, %2;\n"
                 :: "r"(dst), "l"(src), "r"(sz));
}
__device__ __forceinline__ void cp_commit() { asm volatile("cp.async.commit_group;\n"); }
__device__ __forceinline__ void cp_wait0()  { asm volatile("cp.async.wait_group 0;\n"); }
__device__ __forceinline__ void ldsm_x4(unsigned int& r0, unsigned int& r1,
                                        unsigned int& r2, unsigned int& r3, unsigned int a) {
    asm volatile("ldmatrix.sync.aligned.m8n8.x4.shared.b16 {%0,%1,%2,%3},[%4];"
                 : "=r"(r0), "=r"(r1), "=r"(r2), "=r"(r3) : "r"(a));
}
__device__ __forceinline__ void ldsm_x2(unsigned int& r0, unsigned int& r1, unsigned int a) {
    asm volatile("ldmatrix.sync.aligned.m8n8.x2.shared.b16 {%0,%1},[%2];"
                 : "=r"(r0), "=r"(r1) : "r"(a));
}
__device__ __forceinline__ void mma16816(float* c, unsigned int a0, unsigned int a1,
                                         unsigned int a2, unsigned int a3,
                                         unsigned int b0, unsigned int b1) {
    asm volatile("mma.sync.aligned.m16n8k16.row.col.f32.bf16.bf16.f32 "
                 "{%0,%1,%2,%3},{%4,%5,%6,%7},{%8,%9},{%0,%1,%2,%3};"
                 : "+f"(c[0]), "+f"(c[1]), "+f"(c[2]), "+f"(c[3])
                 : "r"(a0), "r"(a1), "r"(a2), "r"(a3), "r"(b0), "r"(b1));
}

// --------------------------- gather indices -----------------------------
__global__ void build_gather(const int* __restrict__ s, const int* __restrict__ t) {
    int r = blockIdx.x * blockDim.x + threadIdx.x;
    if (blockIdx.x == 0 && threadIdx.x < BATCH) g_sbar[threadIdx.x] = 0u;
    if (r >= ROWS) return;
    int sp = r >> 5, b = r & 31;
    g_gidx_enc[r] = s[b * SEQ + sp];
    g_gidx_dec[r] = (sp == 0) ? -1 : t[b * SEQ + sp - 1];
    g_tgtcol[r] = t[b * SEQ + sp];
}

// ------------------- gathered embedding rows -> bf16 ---------------------
__global__ void __launch_bounds__(256) conv_emb(const float* __restrict__ emb) {
    long long e = ((long long)blockIdx.x * blockDim.x + threadIdx.x) * 8;
    if (e >= 2LL * ROWS * EMB) return;
    int which = (e >= (long long)ROWS * EMB);
    long long off = e - (long long)which * ROWS * EMB;
    int r = (int)(off >> 9);
    int c = (int)(off & (EMB - 1));
    int idx = which ? g_gidx_dec[r] : g_gidx_enc[r];
    __nv_bfloat16* dst = which ? g_decA_bf : g_encA_bf;
    __nv_bfloat16 o[8];
    if (idx < 0) {
#pragma unroll
        for (int k = 0; k < 8; k++) o[k] = __float2bfloat16(0.f);
    } else {
        const float* src = emb + (size_t)idx * EMB + c;
        float4 v0 = *(const float4*)src;
        float4 v1 = *(const float4*)(src + 4);
        o[0] = __float2bfloat16(v0.x); o[1] = __float2bfloat16(v0.y);
        o[2] = __float2bfloat16(v0.z); o[3] = __float2bfloat16(v0.w);
        o[4] = __float2bfloat16(v1.x); o[5] = __float2bfloat16(v1.y);
        o[6] = __float2bfloat16(v1.z); o[7] = __float2bfloat16(v1.w);
    }
    *(uint4*)(dst + off) = *(const uint4*)o;
}

// ---------------------------- fp32 -> bf16 (weights) ---------------------
#define CVO1 (G3 * EMB)
#define CVO2 (CVO1 + G3 * EMB)
#define CVO3 (CVO2 + VOC * HID)
#define CVO4 (CVO3 + G3 * HID)
#define CVO5 (CVO4 + G3 * HID)
#define CVEND (CVO5 + G3 * HID)
__global__ void __launch_bounds__(256) conv_all(
    const float* __restrict__ eWih, const float* __restrict__ dWih,
    const float* __restrict__ Wout, const float* __restrict__ eWhh,
    const float* __restrict__ dWhh, const float* __restrict__ dWch)
{
    long long e = ((long long)blockIdx.x * blockDim.x + threadIdx.x) * 8;
    if (e >= CVEND) return;
    const float* src;
    __nv_bfloat16* dst;
    long long off;
    if (e < CVO1)      { src = eWih; dst = g_encWih_bf; off = e; }
    else if (e < CVO2) { src = dWih; dst = g_decWih_bf; off = e - CVO1; }
    else if (e < CVO3) { src = Wout; dst = g_Wout_bf;   off = e - CVO2; }
    else if (e < CVO4) { src = eWhh; dst = g_encWhh_bf; off = e - CVO3; }
    else if (e < CVO5) { src = dWhh; dst = g_decWhh_bf; off = e - CVO4; }
    else               { src = dWch; dst = g_decWch_bf; off = e - CVO5; }
    float4 v0 = *(const float4*)(src + off);
    float4 v1 = *(const float4*)(src + off + 4);
    __nv_bfloat16 o[8];
    o[0] = __float2bfloat16(v0.x); o[1] = __float2bfloat16(v0.y);
    o[2] = __float2bfloat16(v0.z); o[3] = __float2bfloat16(v0.w);
    o[4] = __float2bfloat16(v1.x); o[5] = __float2bfloat16(v1.y);
    o[6] = __float2bfloat16(v1.z); o[7] = __float2bfloat16(v1.w);
    *(uint4*)(dst + off) = *(const uint4*)o;
}

__global__ void conv_attnW(const float* __restrict__ attn_W) {
    int i = blockIdx.x * blockDim.x + threadIdx.x;
    if (i < HID * HID) {
        int j = i >> 10;
        int k = i & 1023;
        g_We_bf[i] = __float2bfloat16(attn_W[(size_t)j * 2048 + 1024 + k]);
        g_Wh_bf[i] = __float2bfloat16(attn_W[(size_t)j * 2048 + k]);
    }
}

// ---------------------------- bf16 HMMA GEMM (R12 2-stage) ---------------
#define PADK 40
__global__ void __launch_bounds__(256) hgemm(int which, const float* __restrict__ bias)
{
    __shared__ __nv_bfloat16 As[2][128][PADK];
    __shared__ __nv_bfloat16 Bs[2][128][PADK];
    const unsigned int STG = 128 * PADK * 2;

    const __nv_bfloat16* A;
    const __nv_bfloat16* Wb;
    float* C;
    int N, K;
    if (which == 0) {
        A = g_encA_bf; Wb = g_encWih_bf; C = g_enc_xg; N = G3; K = EMB;
    } else if (which == 1) {
        A = g_decA_bf; Wb = g_decWih_bf; C = g_dec_xg; N = G3; K = EMB;
    } else if (which == 2) {
        A = g_encouts_bf; Wb = g_We_bf; C = g_enc_energy; N = HID; K = HID;
    } else {
        A = g_dech_bf; Wb = g_Wout_bf; C = (float*)0; N = VOC; K = HID;
    }

    int tid = threadIdx.x;
    int bn = blockIdx.x, bm = blockIdx.y;
    int warp = tid >> 5, lane = tid & 31;
    int wm = warp >> 2, wn = warp & 3;

    int lr = tid >> 2;
    int lc = (tid & 3) * 8;

    const __nv_bfloat16* a0 = A + (size_t)(bm * 128 + lr) * K;
    const __nv_bfloat16* a1 = A + (size_t)(bm * 128 + lr + 64) * K;
    const __nv_bfloat16* b0p = Wb + (size_t)(bn * 128 + lr) * K;
    const __nv_bfloat16* b1p = Wb + (size_t)(bn * 128 + lr + 64) * K;

    unsigned int sa0 = smem_u32(&As[0][lr][lc]);
    unsigned int sa1 = smem_u32(&As[0][lr + 64][lc]);
    unsigned int sb0 = smem_u32(&Bs[0][lr][lc]);
    unsigned int sb1 = smem_u32(&Bs[0][lr + 64][lc]);

    float acc[4][4][4];
#pragma unroll
    for (int mi = 0; mi < 4; mi++) {
#pragma unroll
        for (int ni = 0; ni < 4; ni++) {
#pragma unroll
            for (int q = 0; q < 4; q++) acc[mi][ni][q] = 0.f;
        }
    }

    int arow = wm * 64 + (lane & 15);
    int acol_off = (lane >> 4) * 8;
    int brow = wn * 32 + (lane & 7);
    int bcol_off = ((lane >> 3) & 1) * 8;

    int KT = K / 32;
    cp16(sa0, a0 + lc, true);
    cp16(sa1, a1 + lc, true);
    cp16(sb0, b0p + lc, true);
    cp16(sb1, b1p + lc, true);
    cp_commit();

    int stage = 0;
    for (int kt = 0; kt < KT; kt++) {
        cp_wait0();
        __syncthreads();
        if (kt + 1 < KT) {
            int k = (kt + 1) * 32;
            unsigned int off = (unsigned int)(stage ^ 1) * STG;
            cp16(sa0 + off, a0 + k + lc, true);
            cp16(sa1 + off, a1 + k + lc, true);
            cp16(sb0 + off, b0p + k + lc, true);
            cp16(sb1 + off, b1p + k + lc, true);
            cp_commit();
        }
#pragma unroll
        for (int ks = 0; ks < 32; ks += 16) {
            unsigned int af[4][4];
#pragma unroll
            for (int mi = 0; mi < 4; mi++) {
                unsigned int addr = smem_u32(&As[stage][arow + mi * 16][ks + acol_off]);
                ldsm_x4(af[mi][0], af[mi][1], af[mi][2], af[mi][3], addr);
            }
            unsigned int bfr[4][2];
#pragma unroll
            for (int ni = 0; ni < 4; ni++) {
                unsigned int addr = smem_u32(&Bs[stage][brow + ni * 8][ks + bcol_off]);
                ldsm_x2(bfr[ni][0], bfr[ni][1], addr);
            }
#pragma unroll
            for (int mi = 0; mi < 4; mi++) {
#pragma unroll
                for (int ni = 0; ni < 4; ni++) {
                    mma16816(acc[mi][ni], af[mi][0], af[mi][1], af[mi][2], af[mi][3],
                             bfr[ni][0], bfr[ni][1]);
                }
            }
        }
        stage ^= 1;
    }

    int row_base = bm * 128 + wm * 64;
    int col_base = bn * 128 + wn * 32;

    if (which == 3) {
        float* pm = (float*)&As[0][0][0];
        float* ps = pm + 512;
        float bb2[4][2];
#pragma unroll
        for (int ni = 0; ni < 4; ni++) {
            int c0 = col_base + ni * 8 + (lane & 3) * 2;
            bb2[ni][0] = __ldg(bias + c0);
            bb2[ni][1] = __ldg(bias + c0 + 1);
        }
        __syncthreads();
#pragma unroll
        for (int mi = 0; mi < 4; mi++) {
#pragma unroll
            for (int h = 0; h < 2; h++) {
                int rloc = wm * 64 + mi * 16 + (lane >> 2) + 8 * h;
                int grow = bm * 128 + rloc;
                int tc = g_tgtcol[grow] - bn * 128;
                float v[8];
                float m = -3.4e38f;
#pragma unroll
                for (int ni = 0; ni < 4; ni++) {
#pragma unroll
                    for (int q = 0; q < 2; q++) {
                        float x = acc[mi][ni][2 * h + q] + bb2[ni][q];
                        v[ni * 2 + q] = x;
                        m = fmaxf(m, x);
                        int cl = wn * 32 + ni * 8 + (lane & 3) * 2 + q;
                        if (cl == tc) g_tgtlog[grow] = x;
                    }
                }
                float ssum = 0.f;
#pragma unroll
                for (int k2 = 0; k2 < 8; k2++) ssum += __expf(v[k2] - m);
#pragma unroll
                for (int off = 1; off <= 2; off <<= 1) {
                    float mo = __shfl_xor_sync(0xffffffffu, m, off);
                    float so = __shfl_xor_sync(0xffffffffu, ssum, off);
                    float M = fmaxf(m, mo);
                    ssum = ssum * __expf(m - M) + so * __expf(mo - M);
                    m = M;
                }
                if ((lane & 3) == 0) { pm[rloc * 4 + wn] = m; ps[rloc * 4 + wn] = ssum; }
            }
        }
        __syncthreads();
        if (tid < 128) {
            float m = pm[tid * 4], s2 = ps[tid * 4];
#pragma unroll
            for (int w2 = 1; w2 < 4; w2++) {
                float mo = pm[tid * 4 + w2], so = ps[tid * 4 + w2];
                float M = fmaxf(m, mo);
                s2 = s2 * __expf(m - M) + so * __expf(mo - M);
                m = M;
            }
            g_part[(size_t)(bm * 128 + tid) * LNB + bn] = make_float2(m, s2);
        }
        return;
    }

#pragma unroll
    for (int mi = 0; mi < 4; mi++) {
#pragma unroll
        for (int ni = 0; ni < 4; ni++) {
            int r0 = row_base + mi * 16 + (lane >> 2);
            int c0 = col_base + ni * 8 + (lane & 3) * 2;
            float bv0 = bias ? __ldg(bias + c0) : 0.f;
            float bv1 = bias ? __ldg(bias + c0 + 1) : 0.f;
            float2 v0 = make_float2(acc[mi][ni][0] + bv0, acc[mi][ni][1] + bv1);
            float2 v1 = make_float2(acc[mi][ni][2] + bv0, acc[mi][ni][3] + bv1);
            *(float2*)(C + (size_t)r0 * N + c0) = v0;
            *(float2*)(C + (size_t)(r0 + 8) * N + c0) = v1;
        }
    }
}

// ---------------------------- encoder scan (HMMA) ------------------------
__global__ void __launch_bounds__(SNTHR) enc_scan(const float* __restrict__ bhh)
{
    extern __shared__ char sm[];
    __nv_bfloat16* Wsm = (__nv_bfloat16*)sm;
    __nv_bfloat16* hs  = (__nv_bfloat16*)(sm + ENC_HS_OFF);
    float* Gred        = (float*)(sm + ENC_GRED_OFF);

    int tid = threadIdx.x;
    int w = tid >> 5, lane = tid & 31;
    int mw = w & 1, kw = w >> 1;
    int j0 = blockIdx.x * 8;

    for (int f = tid; f < 24 * 128; f += SNTHR) {
        int r = f >> 7, c = f & 127;
        int grow = (r < 8) ? (j0 + r) : (r < 16) ? (1024 + j0 + r - 8) : (2048 + j0 + r - 16);
        cp16(smem_u32(Wsm + r * RSTRIDE + c * 8), g_encWhh_bf + (size_t)grow * HID + c * 8, true);
    }
    cp_commit();
    for (int i = blockIdx.x * SNTHR + tid; i < BATCH * HID; i += NBLK * SNTHR) {
        g_hbuf[0][i] = 0.f;
        g_hbuf_bf[0][i] = __float2bfloat16(0.f);
    }
    cp_wait0();
    __syncthreads();
    grid_sync();

    int jj = tid & 7, b = tid >> 3;
    float br = 0.f, bz = 0.f, bn_ = 0.f;
    if (tid < 256) {
        br = bhh[j0 + jj]; bz = bhh[1024 + j0 + jj]; bn_ = bhh[2048 + j0 + jj];
    }

    unsigned int aBase = smem_u32(hs) + (unsigned)((mw * 16 + (lane & 15)) * RSTRIDE_B + ((lane >> 4) * 8) * 2);
    unsigned int bBase = smem_u32(Wsm) + (unsigned)((lane & 7) * RSTRIDE_B + (((lane >> 3) & 1) * 8) * 2);

    for (int s = 0; s < SEQ; s++) {
        int hb = s & 1;
        for (int f = tid; f < 32 * 128; f += SNTHR) {
            int r = f >> 7, c = f & 127;
            cp16(smem_u32(hs + r * RSTRIDE + c * 8), g_hbuf_bf[hb] + r * HID + c * 8, true);
        }
        cp_commit(); cp_wait0(); __syncthreads();

        float cG[3][4];
#pragma unroll
        for (int nt = 0; nt < 3; nt++) {
#pragma unroll
            for (int q = 0; q < 4; q++) cG[nt][q] = 0.f;
        }
#pragma unroll
        for (int kt = 0; kt < 8; kt++) {
            int k16 = kw * 8 + kt;
            unsigned int a0, a1, a2, a3;
            ldsm_x4(a0, a1, a2, a3, aBase + k16 * 32);
#pragma unroll
            for (int nt = 0; nt < 3; nt++) {
                unsigned int b0, b1;
                ldsm_x2(b0, b1, bBase + nt * 8 * RSTRIDE_B + k16 * 32);
                mma16816(cG[nt], a0, a1, a2, a3, b0, b1);
            }
        }
        {
            int r0 = lane >> 2, c0 = (lane & 3) * 2;
            int bb = mw * 16 + r0;
#pragma unroll
            for (int nt = 0; nt < 3; nt++) {
                Gred[(kw * 32 + bb) * 24 + nt * 8 + c0]         = cG[nt][0];
                Gred[(kw * 32 + bb) * 24 + nt * 8 + c0 + 1]     = cG[nt][1];
                Gred[(kw * 32 + bb + 8) * 24 + nt * 8 + c0]     = cG[nt][2];
                Gred[(kw * 32 + bb + 8) * 24 + nt * 8 + c0 + 1] = cG[nt][3];
            }
        }
        __syncthreads();
        if (tid < 256) {
            float hr = 0.f, hz = 0.f, hn = 0.f;
#pragma unroll
            for (int k = 0; k < 8; k++) {
                int base2 = (k * 32 + b) * 24;
                hr += Gred[base2 + jj];
                hz += Gred[base2 + 8 + jj];
                hn += Gred[base2 + 16 + jj];
            }
            int row = s * BATCH + b;
            int j = j0 + jj;
            const float* xg = g_enc_xg + (size_t)row * G3;
            float xr = __ldg(xg + j), xz = __ldg(xg + 1024 + j), xn = __ldg(xg + 2048 + j);
            float hprev = g_hbuf[hb][b * HID + j];
            float r = 1.f / (1.f + expf(-(xr + hr + br)));
            float z = 1.f / (1.f + expf(-(xz + hz + bz)));
            float n = tanhf(xn + r * (hn + bn_));
            float hnew = (1.f - z) * n + z * hprev;
            g_hbuf[hb ^ 1][b * HID + j] = hnew;
            __nv_bfloat16 h16 = __float2bfloat16(hnew);
            g_hbuf_bf[hb ^ 1][b * HID + j] = h16;
            g_encouts_bf[(size_t)row * HID + j] = h16;
        }
        grid_sync();
    }
}

// ---------------------------- decoder scan (HMMA) ------------------------
__global__ void __launch_bounds__(SNTHR) dec_scan(const float* __restrict__ bhh,
                                                  const float* __restrict__ attn_v)
{
    extern __shared__ char sm[];
    __nv_bfloat16* Wsm = (__nv_bfloat16*)sm;
    __nv_bfloat16* hs  = (__nv_bfloat16*)(sm + DEC_HS_OFF);
    float* Gred        = (float*)(sm + DEC_GRED_OFF);
    float* whred       = (float*)(sm + DEC_WHRED_OFF);
    float* s_sc        = (float*)(sm + DEC_SSC_OFF);

    int tid = threadIdx.x;
    int w = tid >> 5, lane = tid & 31;
    int mw = w & 1, kw = w >> 1;
    int j0 = blockIdx.x * 8;

    for (int f = tid; f < 56 * 128; f += SNTHR) {
        int r = f >> 7, c = f & 127;
        const __nv_bfloat16* src;
        if (r < 24) {
            int grow = (r < 8) ? (j0 + r) : (r < 16) ? (1024 + j0 + r - 8) : (2048 + j0 + r - 16);
            src = g_decWhh_bf + (size_t)grow * HID;
        } else if (r < 48) {
            int rr = r - 24;
            int grow = (rr < 8) ? (j0 + rr) : (rr < 16) ? (1024 + j0 + rr - 8) : (2048 + j0 + rr - 16);
            src = g_decWch_bf + (size_t)grow * HID;
        } else {
            src = g_Wh_bf + (size_t)(j0 + r - 48) * HID;
        }
        cp16(smem_u32(Wsm + r * RSTRIDE + c * 8), src + c * 8, true);
    }
    cp_commit(); cp_wait0(); __syncthreads();
    grid_sync();

    int jj = tid & 7, b = tid >> 3;
    float br = 0.f, bz = 0.f, bn_ = 0.f;
    if (tid < 256) {
        br = bhh[j0 + jj]; bz = bhh[1024 + j0 + jj]; bn_ = bhh[2048 + j0 + jj];
    }

    unsigned int aBase = smem_u32(hs) + (unsigned)((mw * 16 + (lane & 15)) * RSTRIDE_B + ((lane >> 4) * 8) * 2);
    unsigned int bBase = smem_u32(Wsm) + (unsigned)((lane & 7) * RSTRIDE_B + (((lane >> 3) & 1) * 8) * 2);

    float hr = 0.f, hz = 0.f, hn = 0.f;
    int b2 = blockIdx.x & 31;

    for (int s = 0; s < SEQ; s++) {
        int hb = s & 1;

        for (int f = tid; f < 32 * 128; f += SNTHR) {
            int r = f >> 7, c = f & 127;
            cp16(smem_u32(hs + r * RSTRIDE + c * 8), g_hbuf_bf[hb] + r * HID + c * 8, true);
        }
        cp_commit(); cp_wait0(); __syncthreads();

        float cG[3][4], cW[4];
#pragma unroll
        for (int nt = 0; nt < 3; nt++) {
#pragma unroll
            for (int q = 0; q < 4; q++) cG[nt][q] = 0.f;
        }
#pragma unroll
        for (int q = 0; q < 4; q++) cW[q] = 0.f;
#pragma unroll
        for (int kt = 0; kt < 8; kt++) {
            int k16 = kw * 8 + kt;
            unsigned int a0, a1, a2, a3;
            ldsm_x4(a0, a1, a2, a3, aBase + k16 * 32);
#pragma unroll
            for (int nt = 0; nt < 3; nt++) {
                unsigned int b0, b1;
                ldsm_x2(b0, b1, bBase + nt * 8 * RSTRIDE_B + k16 * 32);
                mma16816(cG[nt], a0, a1, a2, a3, b0, b1);
            }
            unsigned int b0, b1;
            ldsm_x2(b0, b1, bBase + 48 * RSTRIDE_B + k16 * 32);
            mma16816(cW, a0, a1, a2, a3, b0, b1);
        }
        {
            int r0 = lane >> 2, c0 = (lane & 3) * 2;
            int bb = mw * 16 + r0;
#pragma unroll
            for (int nt = 0; nt < 3; nt++) {
                Gred[(kw * 32 + bb) * 24 + nt * 8 + c0]         = cG[nt][0];
                Gred[(kw * 32 + bb) * 24 + nt * 8 + c0 + 1]     = cG[nt][1];
                Gred[(kw * 32 + bb + 8) * 24 + nt * 8 + c0]     = cG[nt][2];
                Gred[(kw * 32 + bb + 8) * 24 + nt * 8 + c0 + 1] = cG[nt][3];
            }
            whred[(kw * 32 + bb) * 8 + c0]         = cW[0];
            whred[(kw * 32 + bb) * 8 + c0 + 1]     = cW[1];
            whred[(kw * 32 + bb + 8) * 8 + c0]     = cW[2];
            whred[(kw * 32 + bb + 8) * 8 + c0 + 1] = cW[3];
        }
        __syncthreads();
        if (tid < 256) {
            float whv = 0.f;
            hr = 0.f; hz = 0.f; hn = 0.f;
#pragma unroll
            for (int k = 0; k < 8; k++) {
                int base2 = k * 32 + b;
                whv += whred[base2 * 8 + jj];
                hr += Gred[base2 * 24 + jj];
                hz += Gred[base2 * 24 + 8 + jj];
                hn += Gred[base2 * 24 + 16 + jj];
            }
            g_wh[b * HID + j0 + jj] = whv;
        }
        grid_sync();

        {
            int sp = (blockIdx.x >> 5) * 16 + w;
            const float* ee = g_enc_energy + (size_t)(sp * BATCH + b2) * HID;
            const float* whp = g_wh + b2 * HID;
            float acc = 0.f;
            for (int k = lane; k < HID; k += 32)
                acc += tanh_approx(__ldg(ee + k) + __ldcg(whp + k)) * __ldg(attn_v + k);
#pragma unroll
            for (int o = 16; o; o >>= 1) acc += __shfl_xor_sync(0xffffffffu, acc, o);
            if (lane == 0) g_scores[b2 * SEQ + sp] = acc;
        }
        group_sync4(b2, 4u * (unsigned)(s + 1));

        {
            int jq = blockIdx.x >> 5;
            if (tid < SEQ) s_sc[tid] = __ldcg(g_scores + b2 * SEQ + tid);
            __syncthreads();
            if (w == 0) {
                float v0 = s_sc[lane], v1 = s_sc[lane + 32];
                float m = fmaxf(v0, v1);
#pragma unroll
                for (int o = 16; o; o >>= 1) m = fmaxf(m, __shfl_xor_sync(0xffffffffu, m, o));
                float e0 = expf(v0 - m), e1 = expf(v1 - m);
                float ssum = e0 + e1;
#pragma unroll
                for (int o = 16; o; o >>= 1) ssum += __shfl_xor_sync(0xffffffffu, ssum, o);
                float inv = 1.f / ssum;
                s_sc[lane] = e0 * inv; s_sc[lane + 32] = e1 * inv;
            }
            __syncthreads();
            if (tid < 256) {
                int jx = jq * 256 + tid;
                float a0 = 0.f, a1 = 0.f, a2 = 0.f, a3 = 0.f;
#pragma unroll 4
                for (int sp = 0; sp < SEQ; sp += 4) {
                    a0 += s_sc[sp]     * __bfloat162float(g_encouts_bf[(size_t)((sp)     * BATCH + b2) * HID + jx]);
                    a1 += s_sc[sp + 1] * __bfloat162float(g_encouts_bf[(size_t)((sp + 1) * BATCH + b2) * HID + jx]);
                    a2 += s_sc[sp + 2] * __bfloat162float(g_encouts_bf[(size_t)((sp + 2) * BATCH + b2) * HID + jx]);
                    a3 += s_sc[sp + 3] * __bfloat162float(g_encouts_bf[(size_t)((sp + 3) * BATCH + b2) * HID + jx]);
                }
                g_ctx_bf[b2 * HID + jx] = __float2bfloat16((a0 + a1) + (a2 + a3));
            }
        }
        grid_sync();

        for (int f = tid; f < 32 * 128; f += SNTHR) {
            int r = f >> 7, c = f & 127;
            cp16(smem_u32(hs + r * RSTRIDE + c * 8), g_ctx_bf + r * HID + c * 8, true);
        }
        cp_commit(); cp_wait0(); __syncthreads();

        float cC[3][4];
#pragma unroll
        for (int nt = 0; nt < 3; nt++) {
#pragma unroll
            for (int q = 0; q < 4; q++) cC[nt][q] = 0.f;
        }
#pragma unroll
        for (int kt = 0; kt < 8; kt++) {
            int k16 = kw * 8 + kt;
            unsigned int a0, a1, a2, a3;
            ldsm_x4(a0, a1, a2, a3, aBase + k16 * 32);
#pragma unroll
            for (int nt = 0; nt < 3; nt++) {
                unsigned int b0, b1;
                ldsm_x2(b0, b1, bBase + (24 + nt * 8) * RSTRIDE_B + k16 * 32);
                mma16816(cC[nt], a0, a1, a2, a3, b0, b1);
            }
        }
        {
            int r0 = lane >> 2, c0 = (lane & 3) * 2;
            int bb = mw * 16 + r0;
#pragma unroll
            for (int nt = 0; nt < 3; nt++) {
                Gred[(kw * 32 + bb) * 24 + nt * 8 + c0]         = cC[nt][0];
                Gred[(kw * 32 + bb) * 24 + nt * 8 + c0 + 1]     = cC[nt][1];
                Gred[(kw * 32 + bb + 8) * 24 + nt * 8 + c0]     = cC[nt][2];
                Gred[(kw * 32 + bb + 8) * 24 + nt * 8 + c0 + 1] = cC[nt][3];
            }
        }
        __syncthreads();
        if (tid < 256) {
            float cr = 0.f, cz = 0.f, cn = 0.f;
#pragma unroll
            for (int k = 0; k < 8; k++) {
                int base2 = (k * 32 + b) * 24;
                cr += Gred[base2 + jj];
                cz += Gred[base2 + 8 + jj];
                cn += Gred[base2 + 16 + jj];
            }
            int row = s * BATCH + b;
            int j = j0 + jj;
            const float* xg = g_dec_xg + (size_t)row * G3;
            float xr = __ldg(xg + j) + cr;
            float xz = __ldg(xg + 1024 + j) + cz;
            float xn = __ldg(xg + 2048 + j) + cn;
            float hprev = g_hbuf[hb][b * HID + j];
            float r = 1.f / (1.f + expf(-(xr + hr + br)));
            float z = 1.f / (1.f + expf(-(xz + hz + bz)));
            float n = tanhf(xn + r * (hn + bn_));
            float hnew = (1.f - z) * n + z * hprev;
            g_hbuf[hb ^ 1][b * HID + j] = hnew;
            __nv_bfloat16 h16 = __float2bfloat16(hnew);
            g_hbuf_bf[hb ^ 1][b * HID + j] = h16;
            g_dech_bf[(size_t)row * HID + j] = h16;
        }
        grid_sync();
    }
}

// ------------------------------- loss ------------------------------------
__global__ void __launch_bounds__(256) loss_combine(const int* __restrict__ tlen)
{
    int w = threadIdx.x >> 5, lane = threadIdx.x & 31;
    int row = blockIdx.x * 8 + w;
    float m = -3.4e38f, s = 0.f;
    for (int i = lane; i < LNB; i += 32) {
        float2 p = g_part[(size_t)row * LNB + i];
        float M = fmaxf(m, p.x);
        s = s * __expf(m - M) + p.y * __expf(p.x - M);
        m = M;
    }
#pragma unroll
    for (int o = 16; o; o >>= 1) {
        float mo = __shfl_xor_sync(0xffffffffu, m, o);
        float so = __shfl_xor_sync(0xffffffffu, s, o);
        float M = fmaxf(m, mo);
        s = s * __expf(m - M) + so * __expf(mo - M);
        m = M;
    }
    if (lane == 0) {
        int sp = row >> 5, b = row & 31;
        float lp = g_tgtlog[row] - m - logf(s);
        g_tok_lp[row] = (sp < tlen[b]) ? lp : 0.f;
    }
}

__global__ void __launch_bounds__(256) loss_final(const int* __restrict__ tlen,
                                                  float* __restrict__ out)
{
    __shared__ float red[256];
    int tid = threadIdx.x;
    float ssum = 0.f;
    for (int r = tid; r < ROWS; r += 256) ssum += g_tok_lp[r];
    red[tid] = ssum; __syncthreads();
    for (int o = 128; o; o >>= 1) {
        if (tid < o) red[tid] += red[tid + o];
        __syncthreads();
    }
    if (tid == 0) {
        float cnt = 0.f;
        for (int b = 0; b < BATCH; b++) cnt += (float)tlen[b];
        out[0] = -red[0] / cnt;
    }
}

// ------------------------------- launch ----------------------------------
extern "C" void kernel_launch(void* const* d_in, const int* in_sizes, int n_in,
                              void* d_out, int out_size)
{
    const int* s         = (const int*)d_in[0];
    const int* t         = (const int*)d_in[1];
    const int* tlen      = (const int*)d_in[2];
    const float* emb     = (const float*)d_in[3];
    const float* enc_Wih = (const float*)d_in[4];
    const float* enc_Whh = (const float*)d_in[5];
    const float* enc_bih = (const float*)d_in[6];
    const float* enc_bhh = (const float*)d_in[7];
    const float* dec_Wih = (const float*)d_in[8];
    const float* dec_Whh = (const float*)d_in[9];
    const float* dec_Wch = (const float*)d_in[10];
    const float* dec_bih = (const float*)d_in[11];
    const float* dec_bhh = (const float*)d_in[12];
    const float* attn_W  = (const float*)d_in[13];
    const float* attn_v  = (const float*)d_in[14];
    const float* Wout    = (const float*)d_in[15];
    const float* bout    = (const float*)d_in[16];
    float* out = (float*)d_out;

    cudaFuncSetAttribute((const void*)enc_scan,
                         cudaFuncAttributeMaxDynamicSharedMemorySize, ENC_SM_TOTAL);
    cudaFuncSetAttribute((const void*)dec_scan,
                         cudaFuncAttributeMaxDynamicSharedMemorySize, DEC_SM_TOTAL);

    build_gather<<<8, 256>>>(s, t);
    conv_emb<<<(2 * ROWS * EMB / 8 + 255) / 256, 256>>>(emb);
    conv_all<<<(int)((CVEND / 8 + 255) / 256), 256>>>(enc_Wih, dec_Wih, Wout,
                                                      enc_Whh, dec_Whh, dec_Wch);
    conv_attnW<<<HID * HID / 256, 256>>>(attn_W);

    hgemm<<<dim3(G3 / 128, ROWS / 128), 256>>>(0, enc_bih);
    hgemm<<<dim3(G3 / 128, ROWS / 128), 256>>>(1, dec_bih);
    enc_scan<<<NBLK, SNTHR, ENC_SM_TOTAL>>>(enc_bhh);
    hgemm<<<dim3(HID / 128, ROWS / 128), 256>>>(2, (const float*)0);
    dec_scan<<<NBLK, SNTHR, DEC_SM_TOTAL>>>(dec_bhh, attn_v);
    hgemm<<<dim3(VOC / 128, ROWS / 128), 256>>>(3, bout);
    loss_combine<<<ROWS / 8, 256>>>(tlen);
    loss_final<<<1, 256>>>(tlen, out);
}

// round 16
// speedup vs baseline: 1.0373x; 1.0266x over previous
#include <cuda_runtime.h>
#include <cuda_bf16.h>
#include <cstdint>
#include <cstddef>
#include <math.h>

#define BATCH 32
#define SEQ   64
#define HID   1024
#define EMB   512
#define VOC   32000
#define G3    3072
#define ROWS  2048   // SEQ*BATCH
#define LNB   250    // VOC/128 logits col-blocks

#define NBLK  128    // persistent scan blocks (HID/8)
#define SNTHR 512    // 16 warps

// padded smem row stride for bf16 weight/activation tiles: 1024 + 8 elems
#define RSTRIDE 1032           // elements
#define RSTRIDE_B 2064         // bytes

// enc smem carve
#define ENC_W_BYTES   (24 * RSTRIDE_B)
#define ENC_HS_OFF    ENC_W_BYTES
#define ENC_GRED_OFF  (ENC_HS_OFF + 32 * RSTRIDE_B)
#define ENC_SM_TOTAL  (ENC_GRED_OFF + 8 * 32 * 24 * 4)

// dec smem carve
#define DEC_W_BYTES   (56 * RSTRIDE_B)
#define DEC_HS_OFF    DEC_W_BYTES
#define DEC_GRED_OFF  (DEC_HS_OFF + 32 * RSTRIDE_B)
#define DEC_WHRED_OFF (DEC_GRED_OFF + 8 * 32 * 24 * 4)
#define DEC_SSC_OFF   (DEC_WHRED_OFF + 8 * 32 * 8 * 4)
#define DEC_SWH_OFF   (DEC_SSC_OFF + SEQ * 4)
#define DEC_SV_OFF    (DEC_SWH_OFF + HID * 4)
#define DEC_SM_TOTAL  (DEC_SV_OFF + HID * 4)   // 222848 (< 228KB limit)

// ------------------------------ scratch ---------------------------------
__device__ float g_enc_xg[ROWS * G3];
__device__ float g_dec_xg[ROWS * G3];
__device__ float g_hbuf[2][BATCH * HID];
__device__ float g_wh[BATCH * HID];
__device__ float g_scores[BATCH * SEQ];
__device__ float g_tok_lp[ROWS];
__device__ float g_tgtlog[ROWS];
__device__ int   g_gidx_enc[ROWS];
__device__ int   g_gidx_dec[ROWS];
__device__ int   g_tgtcol[ROWS];
__device__ __align__(16) float2 g_part[(size_t)ROWS * LNB];
__device__ unsigned g_bar_arrive = 0;
__device__ volatile unsigned g_bar_phase = 0;
__device__ volatile unsigned g_sbar[BATCH];

// bf16 operands
__device__ __align__(16) __nv_bfloat16 g_energy_bf[ROWS * HID];
__device__ __align__(16) __nv_bfloat16 g_encA_bf[ROWS * EMB];
__device__ __align__(16) __nv_bfloat16 g_decA_bf[ROWS * EMB];
__device__ __align__(16) __nv_bfloat16 g_encWih_bf[G3 * EMB];
__device__ __align__(16) __nv_bfloat16 g_decWih_bf[G3 * EMB];
__device__ __align__(16) __nv_bfloat16 g_We_bf[HID * HID];
__device__ __align__(16) __nv_bfloat16 g_Wh_bf[HID * HID];
__device__ __align__(16) __nv_bfloat16 g_Wout_bf[(size_t)VOC * HID];
__device__ __align__(16) __nv_bfloat16 g_encouts_bf[ROWS * HID];
__device__ __align__(16) __nv_bfloat16 g_dech_bf[ROWS * HID];
__device__ __align__(16) __nv_bfloat16 g_encWhh_bf[G3 * HID];
__device__ __align__(16) __nv_bfloat16 g_decWhh_bf[G3 * HID];
__device__ __align__(16) __nv_bfloat16 g_decWch_bf[G3 * HID];
__device__ __align__(16) __nv_bfloat16 g_hbuf_bf[2][BATCH * HID];
__device__ __align__(16) __nv_bfloat16 g_ctx_bf[BATCH * HID];

// ------------------------------ helpers ---------------------------------
__device__ __forceinline__ float tanh_approx(float x) {
    float y; asm("tanh.approx.f32 %0, %1;" : "=f"(y) : "f"(x)); return y;
}

// R12-proven atomic barrier: release by last arriver, single counter.
__device__ __forceinline__ void grid_sync() {
    __syncthreads();
    if (threadIdx.x == 0) {
        __threadfence();
        unsigned ph = g_bar_phase;
        unsigned a = atomicAdd(&g_bar_arrive, 1u);
        if (a == (unsigned)(NBLK - 1)) {
            g_bar_arrive = 0u;
            __threadfence();
            g_bar_phase = ph + 1u;
        } else {
            while (g_bar_phase == ph) { __nanosleep(32); }
        }
    }
    __syncthreads();
}

__device__ __forceinline__ void group_sync4(int b2, unsigned target) {
    __syncthreads();
    if (threadIdx.x == 0) {
        __threadfence();
        atomicAdd((unsigned*)&g_sbar[b2], 1u);
        while (g_sbar[b2] < target) { }
        __threadfence();
    }
    __syncthreads();
}

__device__ __forceinline__ unsigned int smem_u32(const void* p) {
    return (unsigned int)__cvta_generic_to_shared(p);
}
__device__ __forceinline__ void cp16(unsigned int dst, const void* src, bool pred) {
    int sz = pred ? 16 : 0;
    asm volatile("cp.async.cg.shared.global [%0], [%1], 16, %2;\n"
                 :: "r"(dst), "l"(src), "r"(sz));
}
__device__ __forceinline__ void cp_commit() { asm volatile("cp.async.commit_group;\n"); }
__device__ __forceinline__ void cp_wait0()  { asm volatile("cp.async.wait_group 0;\n"); }
__device__ __forceinline__ void ldsm_x4(unsigned int& r0, unsigned int& r1,
                                        unsigned int& r2, unsigned int& r3, unsigned int a) {
    asm volatile("ldmatrix.sync.aligned.m8n8.x4.shared.b16 {%0,%1,%2,%3},[%4];"
                 : "=r"(r0), "=r"(r1), "=r"(r2), "=r"(r3) : "r"(a));
}
__device__ __forceinline__ void ldsm_x2(unsigned int& r0, unsigned int& r1, unsigned int a) {
    asm volatile("ldmatrix.sync.aligned.m8n8.x2.shared.b16 {%0,%1},[%2];"
                 : "=r"(r0), "=r"(r1) : "r"(a));
}
__device__ __forceinline__ void mma16816(float* c, unsigned int a0, unsigned int a1,
                                         unsigned int a2, unsigned int a3,
                                         unsigned int b0, unsigned int b1) {
    asm volatile("mma.sync.aligned.m16n8k16.row.col.f32.bf16.bf16.f32 "
                 "{%0,%1,%2,%3},{%4,%5,%6,%7},{%8,%9},{%0,%1,%2,%3};"
                 : "+f"(c[0]), "+f"(c[1]), "+f"(c[2]), "+f"(c[3])
                 : "r"(a0), "r"(a1), "r"(a2), "r"(a3), "r"(b0), "r"(b1));
}

// --------------------------- gather indices -----------------------------
__global__ void build_gather(const int* __restrict__ s, const int* __restrict__ t) {
    int r = blockIdx.x * blockDim.x + threadIdx.x;
    if (blockIdx.x == 0 && threadIdx.x < BATCH) g_sbar[threadIdx.x] = 0u;
    if (r >= ROWS) return;
    int sp = r >> 5, b = r & 31;
    g_gidx_enc[r] = s[b * SEQ + sp];
    g_gidx_dec[r] = (sp == 0) ? -1 : t[b * SEQ + sp - 1];
    g_tgtcol[r] = t[b * SEQ + sp];
}

// ------------------- gathered embedding rows -> bf16 ---------------------
__global__ void __launch_bounds__(256) conv_emb(const float* __restrict__ emb) {
    long long e = ((long long)blockIdx.x * blockDim.x + threadIdx.x) * 8;
    if (e >= 2LL * ROWS * EMB) return;
    int which = (e >= (long long)ROWS * EMB);
    long long off = e - (long long)which * ROWS * EMB;
    int r = (int)(off >> 9);
    int c = (int)(off & (EMB - 1));
    int idx = which ? g_gidx_dec[r] : g_gidx_enc[r];
    __nv_bfloat16* dst = which ? g_decA_bf : g_encA_bf;
    __nv_bfloat16 o[8];
    if (idx < 0) {
#pragma unroll
        for (int k = 0; k < 8; k++) o[k] = __float2bfloat16(0.f);
    } else {
        const float* src = emb + (size_t)idx * EMB + c;
        float4 v0 = *(const float4*)src;
        float4 v1 = *(const float4*)(src + 4);
        o[0] = __float2bfloat16(v0.x); o[1] = __float2bfloat16(v0.y);
        o[2] = __float2bfloat16(v0.z); o[3] = __float2bfloat16(v0.w);
        o[4] = __float2bfloat16(v1.x); o[5] = __float2bfloat16(v1.y);
        o[6] = __float2bfloat16(v1.z); o[7] = __float2bfloat16(v1.w);
    }
    *(uint4*)(dst + off) = *(const uint4*)o;
}

// ---------------------------- fp32 -> bf16 (weights) ---------------------
#define CVO1 (G3 * EMB)
#define CVO2 (CVO1 + G3 * EMB)
#define CVO3 (CVO2 + VOC * HID)
#define CVO4 (CVO3 + G3 * HID)
#define CVO5 (CVO4 + G3 * HID)
#define CVEND (CVO5 + G3 * HID)
__global__ void __launch_bounds__(256) conv_all(
    const float* __restrict__ eWih, const float* __restrict__ dWih,
    const float* __restrict__ Wout, const float* __restrict__ eWhh,
    const float* __restrict__ dWhh, const float* __restrict__ dWch)
{
    long long e = ((long long)blockIdx.x * blockDim.x + threadIdx.x) * 8;
    if (e >= CVEND) return;
    const float* src;
    __nv_bfloat16* dst;
    long long off;
    if (e < CVO1)      { src = eWih; dst = g_encWih_bf; off = e; }
    else if (e < CVO2) { src = dWih; dst = g_decWih_bf; off = e - CVO1; }
    else if (e < CVO3) { src = Wout; dst = g_Wout_bf;   off = e - CVO2; }
    else if (e < CVO4) { src = eWhh; dst = g_encWhh_bf; off = e - CVO3; }
    else if (e < CVO5) { src = dWhh; dst = g_decWhh_bf; off = e - CVO4; }
    else               { src = dWch; dst = g_decWch_bf; off = e - CVO5; }
    float4 v0 = *(const float4*)(src + off);
    float4 v1 = *(const float4*)(src + off + 4);
    __nv_bfloat16 o[8];
    o[0] = __float2bfloat16(v0.x); o[1] = __float2bfloat16(v0.y);
    o[2] = __float2bfloat16(v0.z); o[3] = __float2bfloat16(v0.w);
    o[4] = __float2bfloat16(v1.x); o[5] = __float2bfloat16(v1.y);
    o[6] = __float2bfloat16(v1.z); o[7] = __float2bfloat16(v1.w);
    *(uint4*)(dst + off) = *(const uint4*)o;
}

__global__ void conv_attnW(const float* __restrict__ attn_W) {
    int i = blockIdx.x * blockDim.x + threadIdx.x;
    if (i < HID * HID) {
        int j = i >> 10;
        int k = i & 1023;
        g_We_bf[i] = __float2bfloat16(attn_W[(size_t)j * 2048 + 1024 + k]);
        g_Wh_bf[i] = __float2bfloat16(attn_W[(size_t)j * 2048 + k]);
    }
}

// ---------------------------- bf16 HMMA GEMM (R12 2-stage) ---------------
// which==2 writes bf16 energy; which==3 fused log-softmax partials.
#define PADK 40
__global__ void __launch_bounds__(256) hgemm(int which, const float* __restrict__ bias)
{
    __shared__ __nv_bfloat16 As[2][128][PADK];
    __shared__ __nv_bfloat16 Bs[2][128][PADK];
    const unsigned int STG = 128 * PADK * 2;

    const __nv_bfloat16* A;
    const __nv_bfloat16* Wb;
    float* C;
    int N, K;
    if (which == 0) {
        A = g_encA_bf; Wb = g_encWih_bf; C = g_enc_xg; N = G3; K = EMB;
    } else if (which == 1) {
        A = g_decA_bf; Wb = g_decWih_bf; C = g_dec_xg; N = G3; K = EMB;
    } else if (which == 2) {
        A = g_encouts_bf; Wb = g_We_bf; C = (float*)0; N = HID; K = HID;
    } else {
        A = g_dech_bf; Wb = g_Wout_bf; C = (float*)0; N = VOC; K = HID;
    }

    int tid = threadIdx.x;
    int bn = blockIdx.x, bm = blockIdx.y;
    int warp = tid >> 5, lane = tid & 31;
    int wm = warp >> 2, wn = warp & 3;

    int lr = tid >> 2;
    int lc = (tid & 3) * 8;

    const __nv_bfloat16* a0 = A + (size_t)(bm * 128 + lr) * K;
    const __nv_bfloat16* a1 = A + (size_t)(bm * 128 + lr + 64) * K;
    const __nv_bfloat16* b0p = Wb + (size_t)(bn * 128 + lr) * K;
    const __nv_bfloat16* b1p = Wb + (size_t)(bn * 128 + lr + 64) * K;

    unsigned int sa0 = smem_u32(&As[0][lr][lc]);
    unsigned int sa1 = smem_u32(&As[0][lr + 64][lc]);
    unsigned int sb0 = smem_u32(&Bs[0][lr][lc]);
    unsigned int sb1 = smem_u32(&Bs[0][lr + 64][lc]);

    float acc[4][4][4];
#pragma unroll
    for (int mi = 0; mi < 4; mi++) {
#pragma unroll
        for (int ni = 0; ni < 4; ni++) {
#pragma unroll
            for (int q = 0; q < 4; q++) acc[mi][ni][q] = 0.f;
        }
    }

    int arow = wm * 64 + (lane & 15);
    int acol_off = (lane >> 4) * 8;
    int brow = wn * 32 + (lane & 7);
    int bcol_off = ((lane >> 3) & 1) * 8;

    int KT = K / 32;
    cp16(sa0, a0 + lc, true);
    cp16(sa1, a1 + lc, true);
    cp16(sb0, b0p + lc, true);
    cp16(sb1, b1p + lc, true);
    cp_commit();

    int stage = 0;
    for (int kt = 0; kt < KT; kt++) {
        cp_wait0();
        __syncthreads();
        if (kt + 1 < KT) {
            int k = (kt + 1) * 32;
            unsigned int off = (unsigned int)(stage ^ 1) * STG;
            cp16(sa0 + off, a0 + k + lc, true);
            cp16(sa1 + off, a1 + k + lc, true);
            cp16(sb0 + off, b0p + k + lc, true);
            cp16(sb1 + off, b1p + k + lc, true);
            cp_commit();
        }
#pragma unroll
        for (int ks = 0; ks < 32; ks += 16) {
            unsigned int af[4][4];
#pragma unroll
            for (int mi = 0; mi < 4; mi++) {
                unsigned int addr = smem_u32(&As[stage][arow + mi * 16][ks + acol_off]);
                ldsm_x4(af[mi][0], af[mi][1], af[mi][2], af[mi][3], addr);
            }
            unsigned int bfr[4][2];
#pragma unroll
            for (int ni = 0; ni < 4; ni++) {
                unsigned int addr = smem_u32(&Bs[stage][brow + ni * 8][ks + bcol_off]);
                ldsm_x2(bfr[ni][0], bfr[ni][1], addr);
            }
#pragma unroll
            for (int mi = 0; mi < 4; mi++) {
#pragma unroll
                for (int ni = 0; ni < 4; ni++) {
                    mma16816(acc[mi][ni], af[mi][0], af[mi][1], af[mi][2], af[mi][3],
                             bfr[ni][0], bfr[ni][1]);
                }
            }
        }
        stage ^= 1;
    }

    int row_base = bm * 128 + wm * 64;
    int col_base = bn * 128 + wn * 32;

    if (which == 3) {
        float* pm = (float*)&As[0][0][0];
        float* ps = pm + 512;
        float bb2[4][2];
#pragma unroll
        for (int ni = 0; ni < 4; ni++) {
            int c0 = col_base + ni * 8 + (lane & 3) * 2;
            bb2[ni][0] = __ldg(bias + c0);
            bb2[ni][1] = __ldg(bias + c0 + 1);
        }
        __syncthreads();
#pragma unroll
        for (int mi = 0; mi < 4; mi++) {
#pragma unroll
            for (int h = 0; h < 2; h++) {
                int rloc = wm * 64 + mi * 16 + (lane >> 2) + 8 * h;
                int grow = bm * 128 + rloc;
                int tc = g_tgtcol[grow] - bn * 128;
                float v[8];
                float m = -3.4e38f;
#pragma unroll
                for (int ni = 0; ni < 4; ni++) {
#pragma unroll
                    for (int q = 0; q < 2; q++) {
                        float x = acc[mi][ni][2 * h + q] + bb2[ni][q];
                        v[ni * 2 + q] = x;
                        m = fmaxf(m, x);
                        int cl = wn * 32 + ni * 8 + (lane & 3) * 2 + q;
                        if (cl == tc) g_tgtlog[grow] = x;
                    }
                }
                float ssum = 0.f;
#pragma unroll
                for (int k2 = 0; k2 < 8; k2++) ssum += __expf(v[k2] - m);
#pragma unroll
                for (int off = 1; off <= 2; off <<= 1) {
                    float mo = __shfl_xor_sync(0xffffffffu, m, off);
                    float so = __shfl_xor_sync(0xffffffffu, ssum, off);
                    float M = fmaxf(m, mo);
                    ssum = ssum * __expf(m - M) + so * __expf(mo - M);
                    m = M;
                }
                if ((lane & 3) == 0) { pm[rloc * 4 + wn] = m; ps[rloc * 4 + wn] = ssum; }
            }
        }
        __syncthreads();
        if (tid < 128) {
            float m = pm[tid * 4], s2 = ps[tid * 4];
#pragma unroll
            for (int w2 = 1; w2 < 4; w2++) {
                float mo = pm[tid * 4 + w2], so = ps[tid * 4 + w2];
                float M = fmaxf(m, mo);
                s2 = s2 * __expf(m - M) + so * __expf(mo - M);
                m = M;
            }
            g_part[(size_t)(bm * 128 + tid) * LNB + bn] = make_float2(m, s2);
        }
        return;
    }

    if (which == 2) {
        // bf16 energy output, no bias
#pragma unroll
        for (int mi = 0; mi < 4; mi++) {
#pragma unroll
            for (int ni = 0; ni < 4; ni++) {
                int r0 = row_base + mi * 16 + (lane >> 2);
                int c0 = col_base + ni * 8 + (lane & 3) * 2;
                __nv_bfloat16 o0[2] = { __float2bfloat16(acc[mi][ni][0]),
                                        __float2bfloat16(acc[mi][ni][1]) };
                __nv_bfloat16 o1[2] = { __float2bfloat16(acc[mi][ni][2]),
                                        __float2bfloat16(acc[mi][ni][3]) };
                *(unsigned*)(g_energy_bf + (size_t)r0 * HID + c0) = *(const unsigned*)o0;
                *(unsigned*)(g_energy_bf + (size_t)(r0 + 8) * HID + c0) = *(const unsigned*)o1;
            }
        }
        return;
    }

#pragma unroll
    for (int mi = 0; mi < 4; mi++) {
#pragma unroll
        for (int ni = 0; ni < 4; ni++) {
            int r0 = row_base + mi * 16 + (lane >> 2);
            int c0 = col_base + ni * 8 + (lane & 3) * 2;
            float bv0 = bias ? __ldg(bias + c0) : 0.f;
            float bv1 = bias ? __ldg(bias + c0 + 1) : 0.f;
            float2 v0 = make_float2(acc[mi][ni][0] + bv0, acc[mi][ni][1] + bv1);
            float2 v1 = make_float2(acc[mi][ni][2] + bv0, acc[mi][ni][3] + bv1);
            *(float2*)(C + (size_t)r0 * N + c0) = v0;
            *(float2*)(C + (size_t)(r0 + 8) * N + c0) = v1;
        }
    }
}

// ---------------------------- encoder scan (HMMA) ------------------------
__global__ void __launch_bounds__(SNTHR) enc_scan(const float* __restrict__ bhh)
{
    extern __shared__ char sm[];
    __nv_bfloat16* Wsm = (__nv_bfloat16*)sm;
    __nv_bfloat16* hs  = (__nv_bfloat16*)(sm + ENC_HS_OFF);
    float* Gred        = (float*)(sm + ENC_GRED_OFF);

    int tid = threadIdx.x;
    int w = tid >> 5, lane = tid & 31;
    int mw = w & 1, kw = w >> 1;
    int j0 = blockIdx.x * 8;

    for (int f = tid; f < 24 * 128; f += SNTHR) {
        int r = f >> 7, c = f & 127;
        int grow = (r < 8) ? (j0 + r) : (r < 16) ? (1024 + j0 + r - 8) : (2048 + j0 + r - 16);
        cp16(smem_u32(Wsm + r * RSTRIDE + c * 8), g_encWhh_bf + (size_t)grow * HID + c * 8, true);
    }
    cp_commit();
    for (int i = blockIdx.x * SNTHR + tid; i < BATCH * HID; i += NBLK * SNTHR) {
        g_hbuf[0][i] = 0.f;
        g_hbuf_bf[0][i] = __float2bfloat16(0.f);
    }
    cp_wait0();
    __syncthreads();
    grid_sync();

    int jj = tid & 7, b = tid >> 3;
    float br = 0.f, bz = 0.f, bn_ = 0.f;
    if (tid < 256) {
        br = bhh[j0 + jj]; bz = bhh[1024 + j0 + jj]; bn_ = bhh[2048 + j0 + jj];
    }

    unsigned int aBase = smem_u32(hs) + (unsigned)((mw * 16 + (lane & 15)) * RSTRIDE_B + ((lane >> 4) * 8) * 2);
    unsigned int bBase = smem_u32(Wsm) + (unsigned)((lane & 7) * RSTRIDE_B + (((lane >> 3) & 1) * 8) * 2);

    for (int s = 0; s < SEQ; s++) {
        int hb = s & 1;
        for (int f = tid; f < 32 * 128; f += SNTHR) {
            int r = f >> 7, c = f & 127;
            cp16(smem_u32(hs + r * RSTRIDE + c * 8), g_hbuf_bf[hb] + r * HID + c * 8, true);
        }
        cp_commit(); cp_wait0(); __syncthreads();

        float cG[3][4];
#pragma unroll
        for (int nt = 0; nt < 3; nt++) {
#pragma unroll
            for (int q = 0; q < 4; q++) cG[nt][q] = 0.f;
        }
#pragma unroll
        for (int kt = 0; kt < 8; kt++) {
            int k16 = kw * 8 + kt;
            unsigned int a0, a1, a2, a3;
            ldsm_x4(a0, a1, a2, a3, aBase + k16 * 32);
#pragma unroll
            for (int nt = 0; nt < 3; nt++) {
                unsigned int b0, b1;
                ldsm_x2(b0, b1, bBase + nt * 8 * RSTRIDE_B + k16 * 32);
                mma16816(cG[nt], a0, a1, a2, a3, b0, b1);
            }
        }
        {
            int r0 = lane >> 2, c0 = (lane & 3) * 2;
            int bb = mw * 16 + r0;
#pragma unroll
            for (int nt = 0; nt < 3; nt++) {
                Gred[(kw * 32 + bb) * 24 + nt * 8 + c0]         = cG[nt][0];
                Gred[(kw * 32 + bb) * 24 + nt * 8 + c0 + 1]     = cG[nt][1];
                Gred[(kw * 32 + bb + 8) * 24 + nt * 8 + c0]     = cG[nt][2];
                Gred[(kw * 32 + bb + 8) * 24 + nt * 8 + c0 + 1] = cG[nt][3];
            }
        }
        __syncthreads();
        if (tid < 256) {
            float hr = 0.f, hz = 0.f, hn = 0.f;
#pragma unroll
            for (int k = 0; k < 8; k++) {
                int base2 = (k * 32 + b) * 24;
                hr += Gred[base2 + jj];
                hz += Gred[base2 + 8 + jj];
                hn += Gred[base2 + 16 + jj];
            }
            int row = s * BATCH + b;
            int j = j0 + jj;
            const float* xg = g_enc_xg + (size_t)row * G3;
            float xr = __ldg(xg + j), xz = __ldg(xg + 1024 + j), xn = __ldg(xg + 2048 + j);
            float hprev = g_hbuf[hb][b * HID + j];
            float r = 1.f / (1.f + expf(-(xr + hr + br)));
            float z = 1.f / (1.f + expf(-(xz + hz + bz)));
            float n = tanhf(xn + r * (hn + bn_));
            float hnew = (1.f - z) * n + z * hprev;
            g_hbuf[hb ^ 1][b * HID + j] = hnew;
            __nv_bfloat16 h16 = __float2bfloat16(hnew);
            g_hbuf_bf[hb ^ 1][b * HID + j] = h16;
            g_encouts_bf[(size_t)row * HID + j] = h16;
        }
        grid_sync();
    }
}

// ---------------------------- decoder scan (HMMA) ------------------------
__global__ void __launch_bounds__(SNTHR) dec_scan(const float* __restrict__ bhh,
                                                  const float* __restrict__ attn_v)
{
    extern __shared__ char sm[];
    __nv_bfloat16* Wsm = (__nv_bfloat16*)sm;
    __nv_bfloat16* hs  = (__nv_bfloat16*)(sm + DEC_HS_OFF);
    float* Gred        = (float*)(sm + DEC_GRED_OFF);
    float* whred       = (float*)(sm + DEC_WHRED_OFF);
    float* s_sc        = (float*)(sm + DEC_SSC_OFF);
    float* s_wh        = (float*)(sm + DEC_SWH_OFF);
    float* s_v         = (float*)(sm + DEC_SV_OFF);

    int tid = threadIdx.x;
    int w = tid >> 5, lane = tid & 31;
    int mw = w & 1, kw = w >> 1;
    int j0 = blockIdx.x * 8;

    for (int f = tid; f < 56 * 128; f += SNTHR) {
        int r = f >> 7, c = f & 127;
        const __nv_bfloat16* src;
        if (r < 24) {
            int grow = (r < 8) ? (j0 + r) : (r < 16) ? (1024 + j0 + r - 8) : (2048 + j0 + r - 16);
            src = g_decWhh_bf + (size_t)grow * HID;
        } else if (r < 48) {
            int rr = r - 24;
            int grow = (rr < 8) ? (j0 + rr) : (rr < 16) ? (1024 + j0 + rr - 8) : (2048 + j0 + rr - 16);
            src = g_decWch_bf + (size_t)grow * HID;
        } else {
            src = g_Wh_bf + (size_t)(j0 + r - 48) * HID;
        }
        cp16(smem_u32(Wsm + r * RSTRIDE + c * 8), src + c * 8, true);
    }
    cp_commit();
    for (int k = tid; k < HID; k += SNTHR) s_v[k] = __ldg(attn_v + k);
    cp_wait0(); __syncthreads();
    grid_sync();

    int jj = tid & 7, b = tid >> 3;
    float br = 0.f, bz = 0.f, bn_ = 0.f;
    if (tid < 256) {
        br = bhh[j0 + jj]; bz = bhh[1024 + j0 + jj]; bn_ = bhh[2048 + j0 + jj];
    }

    unsigned int aBase = smem_u32(hs) + (unsigned)((mw * 16 + (lane & 15)) * RSTRIDE_B + ((lane >> 4) * 8) * 2);
    unsigned int bBase = smem_u32(Wsm) + (unsigned)((lane & 7) * RSTRIDE_B + (((lane >> 3) & 1) * 8) * 2);

    float hr = 0.f, hz = 0.f, hn = 0.f;
    int b2 = blockIdx.x & 31;

    for (int s = 0; s < SEQ; s++) {
        int hb = s & 1;

        for (int f = tid; f < 32 * 128; f += SNTHR) {
            int r = f >> 7, c = f & 127;
            cp16(smem_u32(hs + r * RSTRIDE + c * 8), g_hbuf_bf[hb] + r * HID + c * 8, true);
        }
        cp_commit(); cp_wait0(); __syncthreads();

        float cG[3][4], cW[4];
#pragma unroll
        for (int nt = 0; nt < 3; nt++) {
#pragma unroll
            for (int q = 0; q < 4; q++) cG[nt][q] = 0.f;
        }
#pragma unroll
        for (int q = 0; q < 4; q++) cW[q] = 0.f;
#pragma unroll
        for (int kt = 0; kt < 8; kt++) {
            int k16 = kw * 8 + kt;
            unsigned int a0, a1, a2, a3;
            ldsm_x4(a0, a1, a2, a3, aBase + k16 * 32);
#pragma unroll
            for (int nt = 0; nt < 3; nt++) {
                unsigned int b0, b1;
                ldsm_x2(b0, b1, bBase + nt * 8 * RSTRIDE_B + k16 * 32);
                mma16816(cG[nt], a0, a1, a2, a3, b0, b1);
            }
            unsigned int b0, b1;
            ldsm_x2(b0, b1, bBase + 48 * RSTRIDE_B + k16 * 32);
            mma16816(cW, a0, a1, a2, a3, b0, b1);
        }
        {
            int r0 = lane >> 2, c0 = (lane & 3) * 2;
            int bb = mw * 16 + r0;
#pragma unroll
            for (int nt = 0; nt < 3; nt++) {
                Gred[(kw * 32 + bb) * 24 + nt * 8 + c0]         = cG[nt][0];
                Gred[(kw * 32 + bb) * 24 + nt * 8 + c0 + 1]     = cG[nt][1];
                Gred[(kw * 32 + bb + 8) * 24 + nt * 8 + c0]     = cG[nt][2];
                Gred[(kw * 32 + bb + 8) * 24 + nt * 8 + c0 + 1] = cG[nt][3];
            }
            whred[(kw * 32 + bb) * 8 + c0]         = cW[0];
            whred[(kw * 32 + bb) * 8 + c0 + 1]     = cW[1];
            whred[(kw * 32 + bb + 8) * 8 + c0]     = cW[2];
            whred[(kw * 32 + bb + 8) * 8 + c0 + 1] = cW[3];
        }
        __syncthreads();
        if (tid < 256) {
            float whv = 0.f;
            hr = 0.f; hz = 0.f; hn = 0.f;
#pragma unroll
            for (int k = 0; k < 8; k++) {
                int base2 = k * 32 + b;
                whv += whred[base2 * 8 + jj];
                hr += Gred[base2 * 24 + jj];
                hz += Gred[base2 * 24 + 8 + jj];
                hn += Gred[base2 * 24 + 16 + jj];
            }
            g_wh[b * HID + j0 + jj] = whv;
        }
        grid_sync();

        // stage wh[b2] into smem once, then scores: warp-per-(b2,sp)
        for (int k = tid; k < HID; k += SNTHR)
            s_wh[k] = __ldcg(g_wh + b2 * HID + k);
        __syncthreads();
        {
            int sp = (blockIdx.x >> 5) * 16 + w;
            const __nv_bfloat16* ee = g_energy_bf + (size_t)(sp * BATCH + b2) * HID;
            float acc = 0.f;
            for (int k = lane; k < HID; k += 32)
                acc += tanh_approx(__bfloat162float(ee[k]) + s_wh[k]) * s_v[k];
#pragma unroll
            for (int o = 16; o; o >>= 1) acc += __shfl_xor_sync(0xffffffffu, acc, o);
            if (lane == 0) g_scores[b2 * SEQ + sp] = acc;
        }
        group_sync4(b2, 4u * (unsigned)(s + 1));

        {
            int jq = blockIdx.x >> 5;
            if (tid < SEQ) s_sc[tid] = __ldcg(g_scores + b2 * SEQ + tid);
            __syncthreads();
            if (w == 0) {
                float v0 = s_sc[lane], v1 = s_sc[lane + 32];
                float m = fmaxf(v0, v1);
#pragma unroll
                for (int o = 16; o; o >>= 1) m = fmaxf(m, __shfl_xor_sync(0xffffffffu, m, o));
                float e0 = expf(v0 - m), e1 = expf(v1 - m);
                float ssum = e0 + e1;
#pragma unroll
                for (int o = 16; o; o >>= 1) ssum += __shfl_xor_sync(0xffffffffu, ssum, o);
                float inv = 1.f / ssum;
                s_sc[lane] = e0 * inv; s_sc[lane + 32] = e1 * inv;
            }
            __syncthreads();
            if (tid < 256) {
                int jx = jq * 256 + tid;
                float a0 = 0.f, a1 = 0.f, a2 = 0.f, a3 = 0.f;
#pragma unroll 4
                for (int sp = 0; sp < SEQ; sp += 4) {
                    a0 += s_sc[sp]     * __bfloat162float(g_encouts_bf[(size_t)((sp)     * BATCH + b2) * HID + jx]);
                    a1 += s_sc[sp + 1] * __bfloat162float(g_encouts_bf[(size_t)((sp + 1) * BATCH + b2) * HID + jx]);
                    a2 += s_sc[sp + 2] * __bfloat162float(g_encouts_bf[(size_t)((sp + 2) * BATCH + b2) * HID + jx]);
                    a3 += s_sc[sp + 3] * __bfloat162float(g_encouts_bf[(size_t)((sp + 3) * BATCH + b2) * HID + jx]);
                }
                g_ctx_bf[b2 * HID + jx] = __float2bfloat16((a0 + a1) + (a2 + a3));
            }
        }
        grid_sync();

        for (int f = tid; f < 32 * 128; f += SNTHR) {
            int r = f >> 7, c = f & 127;
            cp16(smem_u32(hs + r * RSTRIDE + c * 8), g_ctx_bf + r * HID + c * 8, true);
        }
        cp_commit(); cp_wait0(); __syncthreads();

        float cC[3][4];
#pragma unroll
        for (int nt = 0; nt < 3; nt++) {
#pragma unroll
            for (int q = 0; q < 4; q++) cC[nt][q] = 0.f;
        }
#pragma unroll
        for (int kt = 0; kt < 8; kt++) {
            int k16 = kw * 8 + kt;
            unsigned int a0, a1, a2, a3;
            ldsm_x4(a0, a1, a2, a3, aBase + k16 * 32);
#pragma unroll
            for (int nt = 0; nt < 3; nt++) {
                unsigned int b0, b1;
                ldsm_x2(b0, b1, bBase + (24 + nt * 8) * RSTRIDE_B + k16 * 32);
                mma16816(cC[nt], a0, a1, a2, a3, b0, b1);
            }
        }
        {
            int r0 = lane >> 2, c0 = (lane & 3) * 2;
            int bb = mw * 16 + r0;
#pragma unroll
            for (int nt = 0; nt < 3; nt++) {
                Gred[(kw * 32 + bb) * 24 + nt * 8 + c0]         = cC[nt][0];
                Gred[(kw * 32 + bb) * 24 + nt * 8 + c0 + 1]     = cC[nt][1];
                Gred[(kw * 32 + bb + 8) * 24 + nt * 8 + c0]     = cC[nt][2];
                Gred[(kw * 32 + bb + 8) * 24 + nt * 8 + c0 + 1] = cC[nt][3];
            }
        }
        __syncthreads();
        if (tid < 256) {
            float cr = 0.f, cz = 0.f, cn = 0.f;
#pragma unroll
            for (int k = 0; k < 8; k++) {
                int base2 = (k * 32 + b) * 24;
                cr += Gred[base2 + jj];
                cz += Gred[base2 + 8 + jj];
                cn += Gred[base2 + 16 + jj];
            }
            int row = s * BATCH + b;
            int j = j0 + jj;
            const float* xg = g_dec_xg + (size_t)row * G3;
            float xr = __ldg(xg + j) + cr;
            float xz = __ldg(xg + 1024 + j) + cz;
            float xn = __ldg(xg + 2048 + j) + cn;
            float hprev = g_hbuf[hb][b * HID + j];
            float r = 1.f / (1.f + expf(-(xr + hr + br)));
            float z = 1.f / (1.f + expf(-(xz + hz + bz)));
            float n = tanhf(xn + r * (hn + bn_));
            float hnew = (1.f - z) * n + z * hprev;
            g_hbuf[hb ^ 1][b * HID + j] = hnew;
            __nv_bfloat16 h16 = __float2bfloat16(hnew);
            g_hbuf_bf[hb ^ 1][b * HID + j] = h16;
            g_dech_bf[(size_t)row * HID + j] = h16;
        }
        grid_sync();
    }
}

// ------------------------------- loss ------------------------------------
__global__ void __launch_bounds__(256) loss_combine(const int* __restrict__ tlen)
{
    int w = threadIdx.x >> 5, lane = threadIdx.x & 31;
    int row = blockIdx.x * 8 + w;
    float m = -3.4e38f, s = 0.f;
    for (int i = lane; i < LNB; i += 32) {
        float2 p = g_part[(size_t)row * LNB + i];
        float M = fmaxf(m, p.x);
        s = s * __expf(m - M) + p.y * __expf(p.x - M);
        m = M;
    }
#pragma unroll
    for (int o = 16; o; o >>= 1) {
        float mo = __shfl_xor_sync(0xffffffffu, m, o);
        float so = __shfl_xor_sync(0xffffffffu, s, o);
        float M = fmaxf(m, mo);
        s = s * __expf(m - M) + so * __expf(mo - M);
        m = M;
    }
    if (lane == 0) {
        int sp = row >> 5, b = row & 31;
        float lp = g_tgtlog[row] - m - logf(s);
        g_tok_lp[row] = (sp < tlen[b]) ? lp : 0.f;
    }
}

__global__ void __launch_bounds__(256) loss_final(const int* __restrict__ tlen,
                                                  float* __restrict__ out)
{
    __shared__ float red[256];
    int tid = threadIdx.x;
    float ssum = 0.f;
    for (int r = tid; r < ROWS; r += 256) ssum += g_tok_lp[r];
    red[tid] = ssum; __syncthreads();
    for (int o = 128; o; o >>= 1) {
        if (tid < o) red[tid] += red[tid + o];
        __syncthreads();
    }
    if (tid == 0) {
        float cnt = 0.f;
        for (int b = 0; b < BATCH; b++) cnt += (float)tlen[b];
        out[0] = -red[0] / cnt;
    }
}

// ------------------------------- launch ----------------------------------
extern "C" void kernel_launch(void* const* d_in, const int* in_sizes, int n_in,
                              void* d_out, int out_size)
{
    const int* s         = (const int*)d_in[0];
    const int* t         = (const int*)d_in[1];
    const int* tlen      = (const int*)d_in[2];
    const float* emb     = (const float*)d_in[3];
    const float* enc_Wih = (const float*)d_in[4];
    const float* enc_Whh = (const float*)d_in[5];
    const float* enc_bih = (const float*)d_in[6];
    const float* enc_bhh = (const float*)d_in[7];
    const float* dec_Wih = (const float*)d_in[8];
    const float* dec_Whh = (const float*)d_in[9];
    const float* dec_Wch = (const float*)d_in[10];
    const float* dec_bih = (const float*)d_in[11];
    const float* dec_bhh = (const float*)d_in[12];
    const float* attn_W  = (const float*)d_in[13];
    const float* attn_v  = (const float*)d_in[14];
    const float* Wout    = (const float*)d_in[15];
    const float* bout    = (const float*)d_in[16];
    float* out = (float*)d_out;

    cudaFuncSetAttribute((const void*)enc_scan,
                         cudaFuncAttributeMaxDynamicSharedMemorySize, ENC_SM_TOTAL);
    cudaFuncSetAttribute((const void*)dec_scan,
                         cudaFuncAttributeMaxDynamicSharedMemorySize, DEC_SM_TOTAL);

    build_gather<<<8, 256>>>(s, t);
    conv_emb<<<(2 * ROWS * EMB / 8 + 255) / 256, 256>>>(emb);
    conv_all<<<(int)((CVEND / 8 + 255) / 256), 256>>>(enc_Wih, dec_Wih, Wout,
                                                      enc_Whh, dec_Whh, dec_Wch);
    conv_attnW<<<HID * HID / 256, 256>>>(attn_W);

    hgemm<<<dim3(G3 / 128, ROWS / 128), 256>>>(0, enc_bih);
    hgemm<<<dim3(G3 / 128, ROWS / 128), 256>>>(1, dec_bih);
    enc_scan<<<NBLK, SNTHR, ENC_SM_TOTAL>>>(enc_bhh);
    hgemm<<<dim3(HID / 128, ROWS / 128), 256>>>(2, (const float*)0);
    dec_scan<<<NBLK, SNTHR, DEC_SM_TOTAL>>>(dec_bhh, attn_v);
    hgemm<<<dim3(VOC / 128, ROWS / 128), 256>>>(3, bout);
    loss_combine<<<ROWS / 8, 256>>>(tlen);
    loss_final<<<1, 256>>>(tlen, out);
}